// round 7
// baseline (speedup 1.0000x reference)
#include <cuda_runtime.h>
#include <math.h>
#include <stdint.h>

#define Bn   128
#define HW   49
#define Cc   2048
#define Dh   2048
#define De   128
#define Nrow (Bn*HW)
#define NPART 98
#define INV_TAU 5.0f

__device__ __forceinline__ uint32_t smem_u32(const void* p) {
    uint32_t a;
    asm("{ .reg .u64 t; cvta.to.shared.u64 t, %1; cvt.u32.u64 %0, t; }" : "=r"(a) : "l"(p));
    return a;
}
__device__ __forceinline__ void cp16(uint32_t dst, const void* src) {
    asm volatile("cp.async.cg.shared.global [%0], [%1], 16;" :: "r"(dst), "l"(src));
}
#define CP_COMMIT() asm volatile("cp.async.commit_group;" ::: "memory")
#define CP_WAIT2()  asm volatile("cp.async.wait_group 2;" ::: "memory")
#define LDMX4(r0, r1, r2, r3, addr)                                            \
    asm volatile("ldmatrix.sync.aligned.m8n8.x4.shared.b16 {%0,%1,%2,%3}, [%4];" \
        : "=r"(r0), "=r"(r1), "=r"(r2), "=r"(r3) : "r"(addr))

__device__ __forceinline__ void imma(int* c, const uint32_t* a, const uint32_t* b) {
    asm volatile("mma.sync.aligned.m16n8k32.row.col.s32.s8.s8.s32 "
        "{%0,%1,%2,%3}, {%4,%5,%6,%7}, {%8,%9}, {%0,%1,%2,%3};"
        : "+r"(c[0]), "+r"(c[1]), "+r"(c[2]), "+r"(c[3])
        : "r"(a[0]), "r"(a[1]), "r"(a[2]), "r"(a[3]), "r"(b[0]), "r"(b[1]));
}

// ===== scratch: int8 interleaved rows [q1(0..K-1) | q0(K..2K-1)], stride 2K ==
__device__ __align__(256) int8_t g_Wd1T[(size_t)Dh*2*Cc], g_mWd1T[(size_t)Dh*2*Cc];
__device__ __align__(256) int8_t g_Wg1T[(size_t)Dh*2*Cc], g_mWg1T[(size_t)Dh*2*Cc];
__device__ __align__(256) int8_t g_Wg2T[De*2*Dh], g_Wd2T[De*2*Dh];
__device__ __align__(256) int8_t g_mWg2T[De*2*Dh], g_mWd2T[De*2*Dh];
__device__ __align__(256) int8_t g_Aq[(size_t)Nrow*2*Cc], g_Ak[(size_t)Nrow*2*Cc];
__device__ __align__(256) int8_t g_pqq[Bn*2*Cc], g_pkq[Bn*2*Cc];
__device__ __align__(256) int8_t g_ghq[2*(size_t)Bn*2*Dh];
__device__ __align__(256) int8_t g_hidq[2*(size_t)Nrow*2*Dh];
__device__ __align__(256) int8_t g_qdmq[Nrow*2*De], g_mtq[Nrow*2*De];
__device__ __align__(256) float g_poolq[Bn*Cc], g_poolk[Bn*Cc];
__device__ __align__(256) float g_gh[2*(size_t)Bn*Dh];
__device__ __align__(256) float g_hid[2*(size_t)Nrow*Dh];
__device__ __align__(256) float g_part[6*(size_t)Nrow*De];
__device__ __align__(256) float g_Spart[(size_t)NPART*Nrow];
__device__ float g_sWd1[Dh], g_smWd1[Dh], g_sWg1[Dh], g_smWg1[Dh];
__device__ float g_sWg2[De], g_sWd2[De], g_smWg2[De], g_smWd2[De];
__device__ float g_sAq[Nrow], g_sAk[Nrow], g_spq[Bn], g_spk[Bn];
__device__ float g_sgh[2*Bn], g_shid[2*Nrow];
__device__ float g_qg[Bn*De], g_kg[Bn*De];
__device__ float g_qd[Nrow*De], g_kd[Nrow*De];
__device__ float g_pos[Nrow], g_lg[Bn], g_ld[Nrow];

// ===== pre-pass ==============================================================
__global__ void colmax(const float* __restrict__ W, float* __restrict__ scale,
                       int K, int N) {
    int n = blockIdx.x * 256 + threadIdx.x;
    if (n >= N) return;
    float m = 0.f;
    for (int k = 0; k < K; k += 4) {
        m = fmaxf(m, fabsf(W[(size_t)k * N + n]));
        m = fmaxf(m, fabsf(W[(size_t)(k+1) * N + n]));
        m = fmaxf(m, fabsf(W[(size_t)(k+2) * N + n]));
        m = fmaxf(m, fabsf(W[(size_t)(k+3) * N + n]));
    }
    scale[n] = fmaxf(m, 1e-20f) / 127.0f;
}

__global__ void transpose_quant(const float* __restrict__ W,
                                const float* __restrict__ scale,
                                int8_t* __restrict__ T, int K, int N) {
    __shared__ float t[32][65];
    int n0 = blockIdx.x * 32, k0 = blockIdx.y * 64;
    int tx = threadIdx.x, ty = threadIdx.y;
#pragma unroll
    for (int r = 0; r < 64; r += 8)
        t[tx][r + ty] = W[(size_t)(k0 + r + ty) * N + n0 + tx];
    __syncthreads();
#pragma unroll
    for (int j = 0; j < 4; j++) {
        int nl = ty + j * 8;
        float inv = 1.0f / scale[n0 + nl];
        float f0 = t[nl][2*tx] * inv, f1 = t[nl][2*tx+1] * inv;
        float a1 = rintf(f0), b1 = rintf(f1);
        size_t o = (size_t)(n0 + nl) * (2 * K) + k0 + 2 * tx;
        char2 c1, c0;
        c1.x = (char)(int)a1; c1.y = (char)(int)b1;
        c0.x = (char)(int)rintf((f0 - a1) * 254.f);
        c0.y = (char)(int)rintf((f1 - b1) * 254.f);
        *(char2*)&T[o]     = c1;
        *(char2*)&T[o + K] = c0;
    }
}

__global__ void pool_kernel(const float* __restrict__ f, float* __restrict__ out) {
    int b = blockIdx.y;
    int c = blockIdx.x * 256 + threadIdx.x;
    const float* p = f + (size_t)b * HW * Cc + c;
    float s = 0.f;
#pragma unroll
    for (int i = 0; i < HW; i++) s += p[(size_t)i * Cc];
    out[(size_t)b * Cc + c] = s * (1.0f / 49.0f);
}

// per-row 2-level quantize of [rows x 2048] fp32
__global__ __launch_bounds__(256)
void quant_rows(const float* __restrict__ X, int8_t* __restrict__ Q,
                float* __restrict__ scale) {
    __shared__ float buf[2048];
    __shared__ float red[256];
    int row = blockIdx.x, tid = threadIdx.x;
    const float* src = X + (size_t)row * 2048;
    float m = 0.f;
#pragma unroll
    for (int i = 0; i < 2; i++) {
        float4 v = ((const float4*)src)[tid * 2 + i];
        *(float4*)&buf[tid * 8 + i * 4] = v;
        m = fmaxf(m, fmaxf(fmaxf(fabsf(v.x), fabsf(v.y)), fmaxf(fabsf(v.z), fabsf(v.w))));
    }
    red[tid] = m; __syncthreads();
    for (int o = 128; o; o >>= 1) { if (tid < o) red[tid] = fmaxf(red[tid], red[tid + o]); __syncthreads(); }
    m = fmaxf(red[0], 1e-20f);
    float inv = 127.0f / m;
    if (tid == 0) scale[row] = m / 127.0f;
#pragma unroll
    for (int i = 0; i < 2; i++) {
        int base = tid * 8 + i * 4;
        char4 c1, c0;
        float f, q1;
        f = buf[base+0]*inv; q1 = rintf(f); c1.x = (char)(int)q1; c0.x = (char)(int)rintf((f-q1)*254.f);
        f = buf[base+1]*inv; q1 = rintf(f); c1.y = (char)(int)q1; c0.y = (char)(int)rintf((f-q1)*254.f);
        f = buf[base+2]*inv; q1 = rintf(f); c1.z = (char)(int)q1; c0.z = (char)(int)rintf((f-q1)*254.f);
        f = buf[base+3]*inv; q1 = rintf(f); c1.w = (char)(int)q1; c0.w = (char)(int)rintf((f-q1)*254.f);
        *(char4*)&Q[(size_t)row * 4096 + base]        = c1;
        *(char4*)&Q[(size_t)row * 4096 + 2048 + base] = c0;
    }
}

// ===== int8 GEMM: D = sA[m]*sB[n]*(q1·p1 + (q1·p0 + q0·p1)/254) =============
// CTA 128(M) x 64(N), K-chunk 64B, 3-stage cp.async.
// EPI 0: fp32 partial at Cf + z*M*N   EPI 1: +bias,relu fp32 at Cf + head*M*N
// EPI 2: exp-rowsum (fixed 1/127 scales) -> Cf[blockIdx.x*M + row]
#define RB 80
#define A1OFF 0
#define A0OFF 10240
#define B1OFF 20480
#define B0OFF 25600
#define STG   30720
#define SM_TOTAL (3*STG)

template<int EPI>
__global__ __launch_bounds__(256, 2)
void gemm_i8(const int8_t* __restrict__ A0g, const int8_t* __restrict__ A1g,
             const int8_t* __restrict__ B0g, const int8_t* __restrict__ B1g,
             const float* __restrict__ sA0, const float* __restrict__ sA1,
             const float* __restrict__ sB0, const float* __restrict__ sB1,
             const float* __restrict__ bias0, const float* __restrict__ bias1,
             float* __restrict__ Cf,
             int M, int N, int ldA, int ldB, int loA, int loB,
             int nbC, int remC, int nzk) {
    extern __shared__ char smem[];
    const uint32_t sb = smem_u32(smem);
    const int tid = threadIdx.x;
    const int wid = tid >> 5, lid = tid & 31;
    const int wm = wid >> 1, wn = wid & 1;
    const int g = lid >> 2, t = lid & 3;
    const int bm = blockIdx.y * 128;
    const int bn = blockIdx.x * 64;
    const int z = blockIdx.z;
    const int head = z / nzk;
    const int kidx = z - head * nzk;
    const int kbeg = (kidx * nbC + min(kidx, remC)) * 64;
    const int nch = nbC + (kidx < remC ? 1 : 0);

    const int8_t* A = (head ? A1g : A0g) + (size_t)bm * ldA + kbeg;
    const int8_t* B = (head ? B1g : B0g) + (size_t)bn * ldB + kbeg;

    int acc1[2][4][4], acc2[2][4][4];
#pragma unroll
    for (int i = 0; i < 2; i++)
#pragma unroll
        for (int j = 0; j < 4; j++)
#pragma unroll
            for (int c = 0; c < 4; c++) { acc1[i][j][c] = 0; acc2[i][j][c] = 0; }

    auto LOAD = [&](int ch, int stg) {
        const int k0 = ch * 64;
        uint32_t st = sb + stg * STG;
#pragma unroll
        for (int s = 0; s < 2; s++) {
            int idx = tid + s * 256;
            int r = idx >> 2, c = idx & 3;
            cp16(st + A1OFF + r*RB + c*16, A + (size_t)r * ldA + k0 + c*16);
            cp16(st + A0OFF + r*RB + c*16, A + (size_t)r * ldA + loA + k0 + c*16);
        }
        {
            int r = tid >> 2, c = tid & 3;
            cp16(st + B1OFF + r*RB + c*16, B + (size_t)r * ldB + k0 + c*16);
            cp16(st + B0OFF + r*RB + c*16, B + (size_t)r * ldB + loB + k0 + c*16);
        }
    };

    for (int p = 0; p < 2; p++) {
        if (p < nch) LOAD(p, p);
        CP_COMMIT();
    }

    const uint32_t a_base = (uint32_t)((wm*32 + (lid & 15)) * RB + ((lid >> 4) & 1) * 16);
    const uint32_t b_base = (uint32_t)((wn*32 + (lid & 7) + ((lid >> 4) & 1) * 8) * RB
                                       + ((lid >> 3) & 1) * 16);

    for (int ch = 0; ch < nch; ch++) {
        if (ch + 2 < nch) LOAD(ch + 2, (ch + 2) % 3);
        CP_COMMIT();
        CP_WAIT2();
        __syncthreads();
        const uint32_t st = sb + (ch % 3) * STG;
#pragma unroll
        for (int ks = 0; ks < 2; ks++) {
            const uint32_t koff = ks * 32;
            uint32_t a1f[2][4], a0f[2][4];
#pragma unroll
            for (int mf = 0; mf < 2; mf++) {
                uint32_t aa = st + a_base + mf * (16*RB) + koff;
                LDMX4(a1f[mf][0], a1f[mf][1], a1f[mf][2], a1f[mf][3], aa + A1OFF);
                LDMX4(a0f[mf][0], a0f[mf][1], a0f[mf][2], a0f[mf][3], aa + A0OFF);
            }
            uint32_t b1f[4][2], b0f[4][2];
#pragma unroll
            for (int jp = 0; jp < 2; jp++) {
                uint32_t bb = st + b_base + jp * (16*RB) + koff;
                LDMX4(b1f[2*jp][0], b1f[2*jp][1], b1f[2*jp+1][0], b1f[2*jp+1][1], bb + B1OFF);
                LDMX4(b0f[2*jp][0], b0f[2*jp][1], b0f[2*jp+1][0], b0f[2*jp+1][1], bb + B0OFF);
            }
#pragma unroll
            for (int mf = 0; mf < 2; mf++)
#pragma unroll
                for (int j = 0; j < 4; j++) {
                    imma(acc1[mf][j], a1f[mf], b1f[j]);
                    imma(acc2[mf][j], a1f[mf], b0f[j]);
                    imma(acc2[mf][j], a0f[mf], b1f[j]);
                }
        }
        __syncthreads();
    }

    if (EPI == 2) {
        const float KS = INV_TAU / 16129.0f;
        float* sm = (float*)smem;
        float rs[2][2];
#pragma unroll
        for (int mf = 0; mf < 2; mf++)
#pragma unroll
            for (int h = 0; h < 2; h++) {
                float s = 0.f;
#pragma unroll
                for (int j = 0; j < 4; j++) {
                    float c0 = (float)acc1[mf][j][2*h]   + (float)acc2[mf][j][2*h]   * (1.f/254.f);
                    float c1 = (float)acc1[mf][j][2*h+1] + (float)acc2[mf][j][2*h+1] * (1.f/254.f);
                    s += __expf(c0 * KS) + __expf(c1 * KS);
                }
                s += __shfl_xor_sync(0xFFFFFFFFu, s, 1);
                s += __shfl_xor_sync(0xFFFFFFFFu, s, 2);
                rs[mf][h] = s;
            }
        __syncthreads();
        if (t == 0) {
#pragma unroll
            for (int mf = 0; mf < 2; mf++)
#pragma unroll
                for (int h = 0; h < 2; h++) {
                    int rl = wm*32 + mf*16 + h*8 + g;
                    sm[rl * 2 + wn] = rs[mf][h];
                }
        }
        __syncthreads();
        if (tid < 128)
            Cf[(size_t)blockIdx.x * M + bm + tid] = sm[tid*2] + sm[tid*2 + 1];
        return;
    }

    const float* sA = head ? sA1 : sA0;
    const float* sB = head ? sB1 : sB0;
    const float* bias = head ? bias1 : bias0;
#pragma unroll
    for (int mf = 0; mf < 2; mf++)
#pragma unroll
        for (int h = 0; h < 2; h++) {
            int row = bm + wm*32 + mf*16 + h*8 + g;
            float sa = sA[row];
#pragma unroll
            for (int j = 0; j < 4; j++) {
                int col = bn + wn*32 + j*8 + 2*t;
                float v0 = ((float)acc1[mf][j][2*h]   + (float)acc2[mf][j][2*h]   * (1.f/254.f)) * sa * sB[col];
                float v1 = ((float)acc1[mf][j][2*h+1] + (float)acc2[mf][j][2*h+1] * (1.f/254.f)) * sa * sB[col+1];
                float2 fv;
                if (EPI == 1) {
                    fv.x = fmaxf(v0 + bias[col], 0.f);
                    fv.y = fmaxf(v1 + bias[col + 1], 0.f);
                    *(float2*)&Cf[(size_t)head * M * N + (size_t)row * N + col] = fv;
                } else {
                    fv.x = v0; fv.y = v1;
                    *(float2*)&Cf[(size_t)z * M * N + (size_t)row * N + col] = fv;
                }
            }
        }
}

template<int RELU>
__global__ void reduce_split(const float* __restrict__ part, const float* __restrict__ bias,
                             float* __restrict__ Cf, int S, size_t MN, int N) {
    size_t i4 = (size_t)blockIdx.x * 256 + threadIdx.x;
    if (i4 * 4 >= MN) return;
    float4 a = {0.f, 0.f, 0.f, 0.f};
    for (int s = 0; s < S; s++) {
        float4 v = *(const float4*)(part + s * MN + i4 * 4);
        a.x += v.x; a.y += v.y; a.z += v.z; a.w += v.w;
    }
    size_t base = i4 * 4;
    int n = (int)(base % N);
    a.x += bias[n]; a.y += bias[n+1]; a.z += bias[n+2]; a.w += bias[n+3];
    if (RELU) {
        a.x = fmaxf(a.x, 0.f); a.y = fmaxf(a.y, 0.f);
        a.z = fmaxf(a.z, 0.f); a.w = fmaxf(a.w, 0.f);
    }
    *(float4*)&Cf[base] = a;
}

// ===== small kernels =========================================================
__global__ void l2norm_kernel(float* __restrict__ x, int rows) {
    int row = blockIdx.x * 8 + threadIdx.y;
    if (row >= rows) return;
    float* p = x + (size_t)row * De;
    int lane = threadIdx.x;
    float4 v = *(float4*)(p + lane * 4);
    float ss = v.x*v.x + v.y*v.y + v.z*v.z + v.w*v.w;
#pragma unroll
    for (int o = 16; o; o >>= 1) ss += __shfl_xor_sync(0xFFFFFFFFu, ss, o);
    float r = 1.0f / sqrtf(fmaxf(ss, 1e-12f));
    v.x *= r; v.y *= r; v.z *= r; v.w *= r;
    *(float4*)(p + lane * 4) = v;
}

__global__ void l2norm_quant(float* __restrict__ x, int8_t* __restrict__ q, int rows) {
    int row = blockIdx.x * 8 + threadIdx.y;
    if (row >= rows) return;
    float* p = x + (size_t)row * De;
    int lane = threadIdx.x;
    float4 v = *(float4*)(p + lane * 4);
    float ss = v.x*v.x + v.y*v.y + v.z*v.z + v.w*v.w;
#pragma unroll
    for (int o = 16; o; o >>= 1) ss += __shfl_xor_sync(0xFFFFFFFFu, ss, o);
    float r = 1.0f / sqrtf(fmaxf(ss, 1e-12f));
    v.x *= r; v.y *= r; v.z *= r; v.w *= r;
    *(float4*)(p + lane * 4) = v;
    char4 c1, c0;
    float f, q1;
    f = v.x*127.f; q1 = rintf(f); c1.x = (char)(int)q1; c0.x = (char)(int)rintf((f-q1)*254.f);
    f = v.y*127.f; q1 = rintf(f); c1.y = (char)(int)q1; c0.y = (char)(int)rintf((f-q1)*254.f);
    f = v.z*127.f; q1 = rintf(f); c1.z = (char)(int)q1; c0.z = (char)(int)rintf((f-q1)*254.f);
    f = v.w*127.f; q1 = rintf(f); c1.w = (char)(int)q1; c0.w = (char)(int)rintf((f-q1)*254.f);
    *(char4*)&q[(size_t)row * 256 + lane * 4]       = c1;
    *(char4*)&q[(size_t)row * 256 + 128 + lane * 4] = c0;
}

__global__ void lg_kernel(const float* __restrict__ qg, const float* __restrict__ kg,
                          float* __restrict__ out) {
    int row = blockIdx.x;
    __shared__ float qs[De];
    __shared__ float red[128];
    int t = threadIdx.x;
    qs[t] = qg[(size_t)row * De + t];
    __syncthreads();
    const float* kp = kg + (size_t)t * De;
    float dot = 0.f;
#pragma unroll 8
    for (int c = 0; c < De; c++) dot = fmaf(qs[c], kp[c], dot);
    float logit = dot * INV_TAU;
    red[t] = __expf(logit); __syncthreads();
    for (int s = 64; s; s >>= 1) { if (t < s) red[t] += red[t + s]; __syncthreads(); }
    float lse = logf(red[0]);
    if (t == row) out[row] = lse - logit;
}

__global__ void match_quant(const float* __restrict__ qd, const float* __restrict__ kd,
                            int8_t* __restrict__ mtq, float* __restrict__ pos) {
    int row = blockIdx.x;
    int b = row / HW;
    __shared__ float qs[De];
    __shared__ float dots[64];
    __shared__ int   s_idx;
    __shared__ float s_val;
    int t = threadIdx.x;
    qs[t] = qd[(size_t)row * De + t];
    __syncthreads();
    if (t < HW) {
        const float* kp = kd + (size_t)(b * HW + t) * De;
        float d = 0.f;
#pragma unroll 8
        for (int c = 0; c < De; c++) d = fmaf(qs[c], kp[c], d);
        dots[t] = d;
    }
    __syncthreads();
    if (t == 0) {
        float bv = dots[0]; int bi = 0;
        for (int j = 1; j < HW; j++)
            if (dots[j] > bv) { bv = dots[j]; bi = j; }
        s_idx = bi; s_val = bv;
    }
    __syncthreads();
    float v = kd[(size_t)(b * HW + s_idx) * De + t];
    float f = v * 127.f, q1 = rintf(f);
    mtq[(size_t)row * 256 + t]       = (char)(int)q1;
    mtq[(size_t)row * 256 + 128 + t] = (char)(int)rintf((f - q1) * 254.f);
    if (t == 0) pos[row] = s_val;
}

__global__ void lse_finish(const float* __restrict__ Spart, const float* __restrict__ pos,
                           float* __restrict__ out) {
    int row = blockIdx.x * 256 + threadIdx.x;
    if (row >= Nrow) return;
    float s = 0.f;
    for (int j = 0; j < NPART; j++) s += Spart[(size_t)j * Nrow + row];
    out[row] = logf(s) - pos[row] * INV_TAU;
}

__global__ void final_kernel(const float* __restrict__ lg, const float* __restrict__ ld,
                             float* __restrict__ out) {
    int t = threadIdx.x;
    float s1 = 0.f, s2 = 0.f;
    if (t < Bn) s1 = lg[t];
    for (int j = t; j < Nrow; j += 256) s2 += ld[j];
    __shared__ float r1[256], r2[256];
    r1[t] = s1; r2[t] = s2; __syncthreads();
    for (int o = 128; o; o >>= 1) {
        if (t < o) { r1[t] += r1[t + o]; r2[t] += r2[t + o]; }
        __syncthreads();
    }
    if (t == 0) out[0] = 0.5f * (r1[0] / (float)Bn) + 0.5f * (r2[0] / (float)Nrow);
}

// ===== host ==================================================================
extern "C" void kernel_launch(void* const* d_in, const int* in_sizes, int n_in,
                              void* d_out, int out_size) {
    const float* feat_q = (const float*)d_in[0];
    const float* feat_k = (const float*)d_in[1];
    const float* Wg1  = (const float*)d_in[2];   const float* bg1 = (const float*)d_in[3];
    const float* Wg2  = (const float*)d_in[4];   const float* bg2 = (const float*)d_in[5];
    const float* Wd1  = (const float*)d_in[6];   const float* bd1 = (const float*)d_in[7];
    const float* Wd2  = (const float*)d_in[8];   const float* bd2 = (const float*)d_in[9];
    const float* mWg1 = (const float*)d_in[10];  const float* mbg1 = (const float*)d_in[11];
    const float* mWg2 = (const float*)d_in[12];  const float* mbg2 = (const float*)d_in[13];
    const float* mWd1 = (const float*)d_in[14];  const float* mbd1 = (const float*)d_in[15];
    const float* mWd2 = (const float*)d_in[16];  const float* mbd2 = (const float*)d_in[17];
    float* out = (float*)d_out;

    cudaFuncSetAttribute(gemm_i8<0>, cudaFuncAttributeMaxDynamicSharedMemorySize, SM_TOTAL);
    cudaFuncSetAttribute(gemm_i8<1>, cudaFuncAttributeMaxDynamicSharedMemorySize, SM_TOTAL);
    cudaFuncSetAttribute(gemm_i8<2>, cudaFuncAttributeMaxDynamicSharedMemorySize, SM_TOTAL);

#define SYM(p, s) cudaGetSymbolAddress((void**)&p, s)
    int8_t *Wd1T, *mWd1T, *Wg1T, *mWg1T, *Wg2T, *Wd2T, *mWg2T, *mWd2T;
    int8_t *Aq, *Ak, *pqq, *pkq, *ghq, *hidq, *qdmq, *mtq;
    float *poolq, *poolk, *gh, *hid, *part, *Spart;
    float *sWd1, *smWd1, *sWg1, *smWg1, *sWg2, *sWd2, *smWg2, *smWd2;
    float *sAq, *sAk, *spq, *spk, *sgh, *shid;
    float *qg, *kg, *qd, *kd, *pos, *lg, *ld;
    SYM(Wd1T, g_Wd1T); SYM(mWd1T, g_mWd1T); SYM(Wg1T, g_Wg1T); SYM(mWg1T, g_mWg1T);
    SYM(Wg2T, g_Wg2T); SYM(Wd2T, g_Wd2T); SYM(mWg2T, g_mWg2T); SYM(mWd2T, g_mWd2T);
    SYM(Aq, g_Aq); SYM(Ak, g_Ak); SYM(pqq, g_pqq); SYM(pkq, g_pkq);
    SYM(ghq, g_ghq); SYM(hidq, g_hidq); SYM(qdmq, g_qdmq); SYM(mtq, g_mtq);
    SYM(poolq, g_poolq); SYM(poolk, g_poolk); SYM(gh, g_gh); SYM(hid, g_hid);
    SYM(part, g_part); SYM(Spart, g_Spart);
    SYM(sWd1, g_sWd1); SYM(smWd1, g_smWd1); SYM(sWg1, g_sWg1); SYM(smWg1, g_smWg1);
    SYM(sWg2, g_sWg2); SYM(sWd2, g_sWd2); SYM(smWg2, g_smWg2); SYM(smWd2, g_smWd2);
    SYM(sAq, g_sAq); SYM(sAk, g_sAk); SYM(spq, g_spq); SYM(spk, g_spk);
    SYM(sgh, g_sgh); SYM(shid, g_shid);
    SYM(qg, g_qg); SYM(kg, g_kg); SYM(qd, g_qd); SYM(kd, g_kd);
    SYM(pos, g_pos); SYM(lg, g_lg); SYM(ld, g_ld);
#undef SYM

    // ---- pre-pass: weight scales + transpose-quant; activation quant ----
    dim3 tb(32, 8);
    colmax<<<Dh/256, 256>>>(Wd1,  sWd1,  Cc, Dh);
    colmax<<<Dh/256, 256>>>(mWd1, smWd1, Cc, Dh);
    colmax<<<Dh/256, 256>>>(Wg1,  sWg1,  Cc, Dh);
    colmax<<<Dh/256, 256>>>(mWg1, smWg1, Cc, Dh);
    colmax<<<1, 256>>>(Wg2,  sWg2,  Dh, De);
    colmax<<<1, 256>>>(Wd2,  sWd2,  Dh, De);
    colmax<<<1, 256>>>(mWg2, smWg2, Dh, De);
    colmax<<<1, 256>>>(mWd2, smWd2, Dh, De);
    transpose_quant<<<dim3(Dh/32, Cc/64), tb>>>(Wd1,  sWd1,  Wd1T,  Cc, Dh);
    transpose_quant<<<dim3(Dh/32, Cc/64), tb>>>(mWd1, smWd1, mWd1T, Cc, Dh);
    transpose_quant<<<dim3(Dh/32, Cc/64), tb>>>(Wg1,  sWg1,  Wg1T,  Cc, Dh);
    transpose_quant<<<dim3(Dh/32, Cc/64), tb>>>(mWg1, smWg1, mWg1T, Cc, Dh);
    transpose_quant<<<dim3(De/32, Dh/64), tb>>>(Wg2,  sWg2,  Wg2T,  Dh, De);
    transpose_quant<<<dim3(De/32, Dh/64), tb>>>(Wd2,  sWd2,  Wd2T,  Dh, De);
    transpose_quant<<<dim3(De/32, Dh/64), tb>>>(mWg2, smWg2, mWg2T, Dh, De);
    transpose_quant<<<dim3(De/32, Dh/64), tb>>>(mWd2, smWd2, mWd2T, Dh, De);

    quant_rows<<<Nrow, 256>>>(feat_q, Aq, sAq);
    quant_rows<<<Nrow, 256>>>(feat_k, Ak, sAk);
    pool_kernel<<<dim3(Cc/256, Bn), 256>>>(feat_q, poolq);
    pool_kernel<<<dim3(Cc/256, Bn), 256>>>(feat_k, poolk);
    quant_rows<<<Bn, 256>>>(poolq, pqq, spq);
    quant_rows<<<Bn, 256>>>(poolk, pkq, spk);

    // ---- global head L1 (merged q+k, split-K 4): [128,2048]x[2048,2048] ----
    gemm_i8<0><<<dim3(Dh/64, 1, 8), 256, SM_TOTAL>>>(pqq, pkq, Wg1T, mWg1T,
        spq, spk, sWg1, smWg1, nullptr, nullptr, part,
        Bn, Dh, 2*Cc, 2*Cc, Cc, Cc, 8, 0, 4);
    reduce_split<1><<<(Bn*Dh/4 + 255)/256, 256>>>(part, bg1, gh, 4, (size_t)Bn*Dh, Dh);
    reduce_split<1><<<(Bn*Dh/4 + 255)/256, 256>>>(part + 4*(size_t)Bn*Dh, mbg1,
        gh + (size_t)Bn*Dh, 4, (size_t)Bn*Dh, Dh);
    quant_rows<<<2*Bn, 256>>>(gh, ghq, sgh);

    // ---- global head L2 (merged, split-K 16) ----
    gemm_i8<0><<<dim3(De/64, 1, 32), 256, SM_TOTAL>>>(ghq, ghq + (size_t)Bn*2*Dh,
        Wg2T, mWg2T, sgh, sgh + Bn, sWg2, smWg2, nullptr, nullptr, part,
        Bn, De, 2*Dh, 2*Dh, Dh, Dh, 2, 0, 16);
    reduce_split<0><<<(Bn*De/4 + 255)/256, 256>>>(part, bg2, qg, 16, (size_t)Bn*De, De);
    reduce_split<0><<<(Bn*De/4 + 255)/256, 256>>>(part + 16*(size_t)Bn*De, mbg2, kg,
        16, (size_t)Bn*De, De);

    l2norm_kernel<<<(Bn + 7)/8, dim3(32, 8)>>>(qg, Bn);
    l2norm_kernel<<<(Bn + 7)/8, dim3(32, 8)>>>(kg, Bn);
    lg_kernel<<<Bn, 128>>>(qg, kg, lg);

    // ---- dense head L1 (merged q+k) ----
    gemm_i8<1><<<dim3(Dh/64, Nrow/128, 2), 256, SM_TOTAL>>>(Aq, Ak, Wd1T, mWd1T,
        sAq, sAk, sWd1, smWd1, bd1, mbd1, hid,
        Nrow, Dh, 2*Cc, 2*Cc, Cc, Cc, 32, 0, 1);
    quant_rows<<<2*Nrow, 256>>>(hid, hidq, shid);

    // ---- dense head L2 (merged, uneven split-K 3: 11+11+10 chunks) ----
    gemm_i8<0><<<dim3(De/64, Nrow/128, 6), 256, SM_TOTAL>>>(hidq,
        hidq + (size_t)Nrow*2*Dh, Wd2T, mWd2T, shid, shid + Nrow, sWd2, smWd2,
        nullptr, nullptr, part, Nrow, De, 2*Dh, 2*Dh, Dh, Dh, 10, 2, 3);
    reduce_split<0><<<(Nrow*De/4 + 255)/256, 256>>>(part, bd2, qd, 3, (size_t)Nrow*De, De);
    reduce_split<0><<<(Nrow*De/4 + 255)/256, 256>>>(part + 3*(size_t)Nrow*De, mbd2, kd,
        3, (size_t)Nrow*De, De);

    l2norm_quant<<<Nrow/8, dim3(32, 8)>>>(qd, qdmq, Nrow);
    l2norm_kernel<<<Nrow/8, dim3(32, 8)>>>(kd, Nrow);

    // ---- matching + dense InfoNCE (fused exp epilogue, fixed 1/127 scales) ----
    match_quant<<<Nrow, 128>>>(qd, kd, mtq, pos);
    gemm_i8<2><<<dim3(NPART, Nrow/128, 1), 256, SM_TOTAL>>>(qdmq, qdmq, mtq, mtq,
        nullptr, nullptr, nullptr, nullptr, nullptr, nullptr, Spart,
        Nrow, Nrow, 2*De, 2*De, De, De, 2, 0, 1);
    lse_finish<<<(Nrow + 255)/256, 256>>>(Spart, pos, ld);

    final_kernel<<<1, 256>>>(lg, ld, out);
}

// round 8
// speedup vs baseline: 1.2838x; 1.2838x over previous
#include <cuda_runtime.h>
#include <math.h>
#include <stdint.h>

#define Bn   128
#define HW   49
#define Cc   2048
#define Dh   2048
#define De   128
#define Nrow (Bn*HW)
#define NPART 98
#define INV_TAU 5.0f

__device__ __forceinline__ uint32_t smem_u32(const void* p) {
    uint32_t a;
    asm("{ .reg .u64 t; cvta.to.shared.u64 t, %1; cvt.u32.u64 %0, t; }" : "=r"(a) : "l"(p));
    return a;
}
__device__ __forceinline__ void cp16(uint32_t dst, const void* src) {
    asm volatile("cp.async.cg.shared.global [%0], [%1], 16;" :: "r"(dst), "l"(src));
}
#define CP_COMMIT() asm volatile("cp.async.commit_group;" ::: "memory")
#define CP_WAIT2()  asm volatile("cp.async.wait_group 2;" ::: "memory")
#define LDMX4(r0, r1, r2, r3, addr)                                            \
    asm volatile("ldmatrix.sync.aligned.m8n8.x4.shared.b16 {%0,%1,%2,%3}, [%4];" \
        : "=r"(r0), "=r"(r1), "=r"(r2), "=r"(r3) : "r"(addr))

__device__ __forceinline__ void imma(int* c, const uint32_t* a, const uint32_t* b) {
    asm volatile("mma.sync.aligned.m16n8k32.row.col.s32.s8.s8.s32 "
        "{%0,%1,%2,%3}, {%4,%5,%6,%7}, {%8,%9}, {%0,%1,%2,%3};"
        : "+r"(c[0]), "+r"(c[1]), "+r"(c[2]), "+r"(c[3])
        : "r"(a[0]), "r"(a[1]), "r"(a[2]), "r"(a[3]), "r"(b[0]), "r"(b[1]));
}

// ===== scratch: int8 interleaved rows [q1(0..K-1) | q0(K..2K-1)], stride 2K ==
__device__ __align__(256) int8_t g_Wd1T[(size_t)Dh*2*Cc], g_mWd1T[(size_t)Dh*2*Cc];
__device__ __align__(256) int8_t g_Wg1T[(size_t)Dh*2*Cc], g_mWg1T[(size_t)Dh*2*Cc];
__device__ __align__(256) int8_t g_Wg2T[De*2*Dh], g_Wd2T[De*2*Dh];
__device__ __align__(256) int8_t g_mWg2T[De*2*Dh], g_mWd2T[De*2*Dh];
__device__ __align__(256) int8_t g_Aq[(size_t)Nrow*2*Cc], g_Ak[(size_t)Nrow*2*Cc];
__device__ __align__(256) int8_t g_pqq[Bn*2*Cc], g_pkq[Bn*2*Cc];
__device__ __align__(256) int8_t g_ghq[2*(size_t)Bn*2*Dh];
__device__ __align__(256) int8_t g_hidq[2*(size_t)Nrow*2*Dh];
__device__ __align__(256) int8_t g_qdmq[Nrow*2*De], g_mtq[Nrow*2*De];
__device__ __align__(256) float g_poolq[Bn*Cc], g_poolk[Bn*Cc];
__device__ __align__(256) float g_gh[2*(size_t)Bn*Dh];
__device__ __align__(256) float g_hid[2*(size_t)Nrow*Dh];
__device__ __align__(256) float g_part[6*(size_t)Nrow*De];
__device__ __align__(256) float g_Spart[(size_t)NPART*Nrow];
__device__ unsigned g_cmax[4*Dh + 4*De];      // colmax partial bits
__device__ float g_sWd1[Dh], g_smWd1[Dh], g_sWg1[Dh], g_smWg1[Dh];
__device__ float g_sWg2[De], g_sWd2[De], g_smWg2[De], g_smWd2[De];
__device__ float g_sAq[Nrow], g_sAk[Nrow], g_spq[Bn], g_spk[Bn];
__device__ float g_sgh[2*Bn], g_shid[2*Nrow];
__device__ float g_qg[Bn*De], g_kg[Bn*De];
__device__ float g_qd[Nrow*De], g_kd[Nrow*De];
__device__ float g_pos[Nrow], g_lg[Bn], g_ld[Nrow];

// ===== pre-pass ==============================================================
__global__ void zero_u32(unsigned* __restrict__ p, int n) {
    int i = blockIdx.x * 256 + threadIdx.x;
    if (i < n) p[i] = 0u;
}

// parallel per-column |max|: grid (ceil(N/256), K/128); coalesced rows.
__global__ void colmax_part(const float* __restrict__ W, unsigned* __restrict__ mx,
                            int K, int N) {
    int n = blockIdx.x * 256 + threadIdx.x;
    if (n >= N) return;
    int k0 = blockIdx.y * 128;
    float m = 0.f;
#pragma unroll 4
    for (int k = k0; k < k0 + 128; k++)
        m = fmaxf(m, fabsf(W[(size_t)k * N + n]));
    atomicMax(&mx[n], __float_as_uint(m));
}

__global__ void colmax_fin(const unsigned* __restrict__ mx, float* __restrict__ scale,
                           int N) {
    int n = blockIdx.x * 256 + threadIdx.x;
    if (n < N) scale[n] = fmaxf(__uint_as_float(mx[n]), 1e-20f) / 127.0f;
}

__global__ void transpose_quant(const float* __restrict__ W,
                                const float* __restrict__ scale,
                                int8_t* __restrict__ T, int K, int N) {
    __shared__ float t[32][65];
    int n0 = blockIdx.x * 32, k0 = blockIdx.y * 64;
    int tx = threadIdx.x, ty = threadIdx.y;
#pragma unroll
    for (int r = 0; r < 64; r += 8)
        t[tx][r + ty] = W[(size_t)(k0 + r + ty) * N + n0 + tx];
    __syncthreads();
#pragma unroll
    for (int j = 0; j < 4; j++) {
        int nl = ty + j * 8;
        float inv = 1.0f / scale[n0 + nl];
        float f0 = t[nl][2*tx] * inv, f1 = t[nl][2*tx+1] * inv;
        float a1 = rintf(f0), b1 = rintf(f1);
        size_t o = (size_t)(n0 + nl) * (2 * K) + k0 + 2 * tx;
        char2 c1, c0;
        c1.x = (char)(int)a1; c1.y = (char)(int)b1;
        c0.x = (char)(int)rintf((f0 - a1) * 254.f);
        c0.y = (char)(int)rintf((f1 - b1) * 254.f);
        *(char2*)&T[o]     = c1;
        *(char2*)&T[o + K] = c0;
    }
}

__global__ void pool_kernel(const float* __restrict__ f, float* __restrict__ out) {
    int b = blockIdx.y;
    int c = blockIdx.x * 256 + threadIdx.x;
    const float* p = f + (size_t)b * HW * Cc + c;
    float s = 0.f;
#pragma unroll
    for (int i = 0; i < HW; i++) s += p[(size_t)i * Cc];
    out[(size_t)b * Cc + c] = s * (1.0f / 49.0f);
}

// per-row 2-level quantize of [rows x 2048] fp32
__global__ __launch_bounds__(256)
void quant_rows(const float* __restrict__ X, int8_t* __restrict__ Q,
                float* __restrict__ scale) {
    __shared__ float buf[2048];
    __shared__ float red[256];
    int row = blockIdx.x, tid = threadIdx.x;
    const float* src = X + (size_t)row * 2048;
    float m = 0.f;
#pragma unroll
    for (int i = 0; i < 2; i++) {
        float4 v = ((const float4*)src)[tid * 2 + i];
        *(float4*)&buf[tid * 8 + i * 4] = v;
        m = fmaxf(m, fmaxf(fmaxf(fabsf(v.x), fabsf(v.y)), fmaxf(fabsf(v.z), fabsf(v.w))));
    }
    red[tid] = m; __syncthreads();
    for (int o = 128; o; o >>= 1) { if (tid < o) red[tid] = fmaxf(red[tid], red[tid + o]); __syncthreads(); }
    m = fmaxf(red[0], 1e-20f);
    float inv = 127.0f / m;
    if (tid == 0) scale[row] = m / 127.0f;
#pragma unroll
    for (int i = 0; i < 2; i++) {
        int base = tid * 8 + i * 4;
        char4 c1, c0;
        float f, q1;
        f = buf[base+0]*inv; q1 = rintf(f); c1.x = (char)(int)q1; c0.x = (char)(int)rintf((f-q1)*254.f);
        f = buf[base+1]*inv; q1 = rintf(f); c1.y = (char)(int)q1; c0.y = (char)(int)rintf((f-q1)*254.f);
        f = buf[base+2]*inv; q1 = rintf(f); c1.z = (char)(int)q1; c0.z = (char)(int)rintf((f-q1)*254.f);
        f = buf[base+3]*inv; q1 = rintf(f); c1.w = (char)(int)q1; c0.w = (char)(int)rintf((f-q1)*254.f);
        *(char4*)&Q[(size_t)row * 4096 + base]        = c1;
        *(char4*)&Q[(size_t)row * 4096 + 2048 + base] = c0;
    }
}

// ===== int8 GEMM: D = sA[m]*sB[n]*(q1·p1 + (q1·p0 + q0·p1)/254) =============
// CTA 128(M) x 64(N), K-chunk 64B, 3-stage cp.async.
// EPI 0: fp32 partial at Cf + z*M*N   EPI 1: +bias,relu fp32 at Cf + head*M*N
// EPI 2: exp-rowsum (fixed 1/127 scales) -> Cf[blockIdx.x*M + row]
#define RB 80
#define A1OFF 0
#define A0OFF 10240
#define B1OFF 20480
#define B0OFF 25600
#define STG   30720
#define SM_TOTAL (3*STG)

template<int EPI>
__global__ __launch_bounds__(256, 2)
void gemm_i8(const int8_t* __restrict__ A0g, const int8_t* __restrict__ A1g,
             const int8_t* __restrict__ B0g, const int8_t* __restrict__ B1g,
             const float* __restrict__ sA0, const float* __restrict__ sA1,
             const float* __restrict__ sB0, const float* __restrict__ sB1,
             const float* __restrict__ bias0, const float* __restrict__ bias1,
             float* __restrict__ Cf,
             int M, int N, int ldA, int ldB, int loA, int loB,
             int nbC, int remC, int nzk) {
    extern __shared__ char smem[];
    const uint32_t sb = smem_u32(smem);
    const int tid = threadIdx.x;
    const int wid = tid >> 5, lid = tid & 31;
    const int wm = wid >> 1, wn = wid & 1;
    const int g = lid >> 2, t = lid & 3;
    const int bm = blockIdx.y * 128;
    const int bn = blockIdx.x * 64;
    const int z = blockIdx.z;
    const int head = z / nzk;
    const int kidx = z - head * nzk;
    const int kbeg = (kidx * nbC + min(kidx, remC)) * 64;
    const int nch = nbC + (kidx < remC ? 1 : 0);

    const int8_t* A = (head ? A1g : A0g) + (size_t)bm * ldA + kbeg;
    const int8_t* B = (head ? B1g : B0g) + (size_t)bn * ldB + kbeg;

    int acc1[2][4][4], acc2[2][4][4];
#pragma unroll
    for (int i = 0; i < 2; i++)
#pragma unroll
        for (int j = 0; j < 4; j++)
#pragma unroll
            for (int c = 0; c < 4; c++) { acc1[i][j][c] = 0; acc2[i][j][c] = 0; }

    auto LOAD = [&](int ch, int stg) {
        const int k0 = ch * 64;
        uint32_t st = sb + stg * STG;
#pragma unroll
        for (int s = 0; s < 2; s++) {
            int idx = tid + s * 256;
            int r = idx >> 2, c = idx & 3;
            cp16(st + A1OFF + r*RB + c*16, A + (size_t)r * ldA + k0 + c*16);
            cp16(st + A0OFF + r*RB + c*16, A + (size_t)r * ldA + loA + k0 + c*16);
        }
        {
            int r = tid >> 2, c = tid & 3;
            cp16(st + B1OFF + r*RB + c*16, B + (size_t)r * ldB + k0 + c*16);
            cp16(st + B0OFF + r*RB + c*16, B + (size_t)r * ldB + loB + k0 + c*16);
        }
    };

    for (int p = 0; p < 2; p++) {
        if (p < nch) LOAD(p, p);
        CP_COMMIT();
    }

    const uint32_t a_base = (uint32_t)((wm*32 + (lid & 15)) * RB + ((lid >> 4) & 1) * 16);
    const uint32_t b_base = (uint32_t)((wn*32 + (lid & 7) + ((lid >> 4) & 1) * 8) * RB
                                       + ((lid >> 3) & 1) * 16);

    for (int ch = 0; ch < nch; ch++) {
        if (ch + 2 < nch) LOAD(ch + 2, (ch + 2) % 3);
        CP_COMMIT();
        CP_WAIT2();
        __syncthreads();
        const uint32_t st = sb + (ch % 3) * STG;
#pragma unroll
        for (int ks = 0; ks < 2; ks++) {
            const uint32_t koff = ks * 32;
            uint32_t a1f[2][4], a0f[2][4];
#pragma unroll
            for (int mf = 0; mf < 2; mf++) {
                uint32_t aa = st + a_base + mf * (16*RB) + koff;
                LDMX4(a1f[mf][0], a1f[mf][1], a1f[mf][2], a1f[mf][3], aa + A1OFF);
                LDMX4(a0f[mf][0], a0f[mf][1], a0f[mf][2], a0f[mf][3], aa + A0OFF);
            }
            uint32_t b1f[4][2], b0f[4][2];
#pragma unroll
            for (int jp = 0; jp < 2; jp++) {
                uint32_t bb = st + b_base + jp * (16*RB) + koff;
                LDMX4(b1f[2*jp][0], b1f[2*jp][1], b1f[2*jp+1][0], b1f[2*jp+1][1], bb + B1OFF);
                LDMX4(b0f[2*jp][0], b0f[2*jp][1], b0f[2*jp+1][0], b0f[2*jp+1][1], bb + B0OFF);
            }
#pragma unroll
            for (int mf = 0; mf < 2; mf++)
#pragma unroll
                for (int j = 0; j < 4; j++) {
                    imma(acc1[mf][j], a1f[mf], b1f[j]);
                    imma(acc2[mf][j], a1f[mf], b0f[j]);
                    imma(acc2[mf][j], a0f[mf], b1f[j]);
                }
        }
        __syncthreads();
    }

    if (EPI == 2) {
        const float KS = INV_TAU / 16129.0f;
        float* sm = (float*)smem;
        float rs[2][2];
#pragma unroll
        for (int mf = 0; mf < 2; mf++)
#pragma unroll
            for (int h = 0; h < 2; h++) {
                float s = 0.f;
#pragma unroll
                for (int j = 0; j < 4; j++) {
                    float c0 = (float)acc1[mf][j][2*h]   + (float)acc2[mf][j][2*h]   * (1.f/254.f);
                    float c1 = (float)acc1[mf][j][2*h+1] + (float)acc2[mf][j][2*h+1] * (1.f/254.f);
                    s += __expf(c0 * KS) + __expf(c1 * KS);
                }
                s += __shfl_xor_sync(0xFFFFFFFFu, s, 1);
                s += __shfl_xor_sync(0xFFFFFFFFu, s, 2);
                rs[mf][h] = s;
            }
        __syncthreads();
        if (t == 0) {
#pragma unroll
            for (int mf = 0; mf < 2; mf++)
#pragma unroll
                for (int h = 0; h < 2; h++) {
                    int rl = wm*32 + mf*16 + h*8 + g;
                    sm[rl * 2 + wn] = rs[mf][h];
                }
        }
        __syncthreads();
        if (tid < 128)
            Cf[(size_t)blockIdx.x * M + bm + tid] = sm[tid*2] + sm[tid*2 + 1];
        return;
    }

    const float* sA = head ? sA1 : sA0;
    const float* sB = head ? sB1 : sB0;
    const float* bias = head ? bias1 : bias0;
#pragma unroll
    for (int mf = 0; mf < 2; mf++)
#pragma unroll
        for (int h = 0; h < 2; h++) {
            int row = bm + wm*32 + mf*16 + h*8 + g;
            float sa = sA[row];
#pragma unroll
            for (int j = 0; j < 4; j++) {
                int col = bn + wn*32 + j*8 + 2*t;
                float v0 = ((float)acc1[mf][j][2*h]   + (float)acc2[mf][j][2*h]   * (1.f/254.f)) * sa * sB[col];
                float v1 = ((float)acc1[mf][j][2*h+1] + (float)acc2[mf][j][2*h+1] * (1.f/254.f)) * sa * sB[col+1];
                float2 fv;
                if (EPI == 1) {
                    fv.x = fmaxf(v0 + bias[col], 0.f);
                    fv.y = fmaxf(v1 + bias[col + 1], 0.f);
                    *(float2*)&Cf[(size_t)head * M * N + (size_t)row * N + col] = fv;
                } else {
                    fv.x = v0; fv.y = v1;
                    *(float2*)&Cf[(size_t)z * M * N + (size_t)row * N + col] = fv;
                }
            }
        }
}

template<int RELU>
__global__ void reduce_split(const float* __restrict__ part, const float* __restrict__ bias,
                             float* __restrict__ Cf, int S, size_t MN, int N) {
    size_t i4 = (size_t)blockIdx.x * 256 + threadIdx.x;
    if (i4 * 4 >= MN) return;
    float4 a = {0.f, 0.f, 0.f, 0.f};
    for (int s = 0; s < S; s++) {
        float4 v = *(const float4*)(part + s * MN + i4 * 4);
        a.x += v.x; a.y += v.y; a.z += v.z; a.w += v.w;
    }
    size_t base = i4 * 4;
    int n = (int)(base % N);
    a.x += bias[n]; a.y += bias[n+1]; a.z += bias[n+2]; a.w += bias[n+3];
    if (RELU) {
        a.x = fmaxf(a.x, 0.f); a.y = fmaxf(a.y, 0.f);
        a.z = fmaxf(a.z, 0.f); a.w = fmaxf(a.w, 0.f);
    }
    *(float4*)&Cf[base] = a;
}

// ===== small kernels =========================================================
__global__ void l2norm_kernel(float* __restrict__ x, int rows) {
    int row = blockIdx.x * 8 + threadIdx.y;
    if (row >= rows) return;
    float* p = x + (size_t)row * De;
    int lane = threadIdx.x;
    float4 v = *(float4*)(p + lane * 4);
    float ss = v.x*v.x + v.y*v.y + v.z*v.z + v.w*v.w;
#pragma unroll
    for (int o = 16; o; o >>= 1) ss += __shfl_xor_sync(0xFFFFFFFFu, ss, o);
    float r = 1.0f / sqrtf(fmaxf(ss, 1e-12f));
    v.x *= r; v.y *= r; v.z *= r; v.w *= r;
    *(float4*)(p + lane * 4) = v;
}

__global__ void l2norm_quant(float* __restrict__ x, int8_t* __restrict__ q, int rows) {
    int row = blockIdx.x * 8 + threadIdx.y;
    if (row >= rows) return;
    float* p = x + (size_t)row * De;
    int lane = threadIdx.x;
    float4 v = *(float4*)(p + lane * 4);
    float ss = v.x*v.x + v.y*v.y + v.z*v.z + v.w*v.w;
#pragma unroll
    for (int o = 16; o; o >>= 1) ss += __shfl_xor_sync(0xFFFFFFFFu, ss, o);
    float r = 1.0f / sqrtf(fmaxf(ss, 1e-12f));
    v.x *= r; v.y *= r; v.z *= r; v.w *= r;
    *(float4*)(p + lane * 4) = v;
    char4 c1, c0;
    float f, q1;
    f = v.x*127.f; q1 = rintf(f); c1.x = (char)(int)q1; c0.x = (char)(int)rintf((f-q1)*254.f);
    f = v.y*127.f; q1 = rintf(f); c1.y = (char)(int)q1; c0.y = (char)(int)rintf((f-q1)*254.f);
    f = v.z*127.f; q1 = rintf(f); c1.z = (char)(int)q1; c0.z = (char)(int)rintf((f-q1)*254.f);
    f = v.w*127.f; q1 = rintf(f); c1.w = (char)(int)q1; c0.w = (char)(int)rintf((f-q1)*254.f);
    *(char4*)&q[(size_t)row * 256 + lane * 4]       = c1;
    *(char4*)&q[(size_t)row * 256 + 128 + lane * 4] = c0;
}

__global__ void lg_kernel(const float* __restrict__ qg, const float* __restrict__ kg,
                          float* __restrict__ out) {
    int row = blockIdx.x;
    __shared__ float qs[De];
    __shared__ float red[128];
    int t = threadIdx.x;
    qs[t] = qg[(size_t)row * De + t];
    __syncthreads();
    const float* kp = kg + (size_t)t * De;
    float dot = 0.f;
#pragma unroll 8
    for (int c = 0; c < De; c++) dot = fmaf(qs[c], kp[c], dot);
    float logit = dot * INV_TAU;
    red[t] = __expf(logit); __syncthreads();
    for (int s = 64; s; s >>= 1) { if (t < s) red[t] += red[t + s]; __syncthreads(); }
    float lse = logf(red[0]);
    if (t == row) out[row] = lse - logit;
}

__global__ void match_quant(const float* __restrict__ qd, const float* __restrict__ kd,
                            int8_t* __restrict__ mtq, float* __restrict__ pos) {
    int row = blockIdx.x;
    int b = row / HW;
    __shared__ float qs[De];
    __shared__ float dots[64];
    __shared__ int   s_idx;
    __shared__ float s_val;
    int t = threadIdx.x;
    qs[t] = qd[(size_t)row * De + t];
    __syncthreads();
    if (t < HW) {
        const float* kp = kd + (size_t)(b * HW + t) * De;
        float d = 0.f;
#pragma unroll 8
        for (int c = 0; c < De; c++) d = fmaf(qs[c], kp[c], d);
        dots[t] = d;
    }
    __syncthreads();
    if (t == 0) {
        float bv = dots[0]; int bi = 0;
        for (int j = 1; j < HW; j++)
            if (dots[j] > bv) { bv = dots[j]; bi = j; }
        s_idx = bi; s_val = bv;
    }
    __syncthreads();
    float v = kd[(size_t)(b * HW + s_idx) * De + t];
    float f = v * 127.f, q1 = rintf(f);
    mtq[(size_t)row * 256 + t]       = (char)(int)q1;
    mtq[(size_t)row * 256 + 128 + t] = (char)(int)rintf((f - q1) * 254.f);
    if (t == 0) pos[row] = s_val;
}

__global__ void lse_finish(const float* __restrict__ Spart, const float* __restrict__ pos,
                           float* __restrict__ out) {
    int row = blockIdx.x * 256 + threadIdx.x;
    if (row >= Nrow) return;
    float s = 0.f;
    for (int j = 0; j < NPART; j++) s += Spart[(size_t)j * Nrow + row];
    out[row] = logf(s) - pos[row] * INV_TAU;
}

__global__ void final_kernel(const float* __restrict__ lg, const float* __restrict__ ld,
                             float* __restrict__ out) {
    int t = threadIdx.x;
    float s1 = 0.f, s2 = 0.f;
    if (t < Bn) s1 = lg[t];
    for (int j = t; j < Nrow; j += 256) s2 += ld[j];
    __shared__ float r1[256], r2[256];
    r1[t] = s1; r2[t] = s2; __syncthreads();
    for (int o = 128; o; o >>= 1) {
        if (t < o) { r1[t] += r1[t + o]; r2[t] += r2[t + o]; }
        __syncthreads();
    }
    if (t == 0) out[0] = 0.5f * (r1[0] / (float)Bn) + 0.5f * (r2[0] / (float)Nrow);
}

// ===== host ==================================================================
extern "C" void kernel_launch(void* const* d_in, const int* in_sizes, int n_in,
                              void* d_out, int out_size) {
    const float* feat_q = (const float*)d_in[0];
    const float* feat_k = (const float*)d_in[1];
    const float* Wg1  = (const float*)d_in[2];   const float* bg1 = (const float*)d_in[3];
    const float* Wg2  = (const float*)d_in[4];   const float* bg2 = (const float*)d_in[5];
    const float* Wd1  = (const float*)d_in[6];   const float* bd1 = (const float*)d_in[7];
    const float* Wd2  = (const float*)d_in[8];   const float* bd2 = (const float*)d_in[9];
    const float* mWg1 = (const float*)d_in[10];  const float* mbg1 = (const float*)d_in[11];
    const float* mWg2 = (const float*)d_in[12];  const float* mbg2 = (const float*)d_in[13];
    const float* mWd1 = (const float*)d_in[14];  const float* mbd1 = (const float*)d_in[15];
    const float* mWd2 = (const float*)d_in[16];  const float* mbd2 = (const float*)d_in[17];
    float* out = (float*)d_out;

    cudaFuncSetAttribute(gemm_i8<0>, cudaFuncAttributeMaxDynamicSharedMemorySize, SM_TOTAL);
    cudaFuncSetAttribute(gemm_i8<1>, cudaFuncAttributeMaxDynamicSharedMemorySize, SM_TOTAL);
    cudaFuncSetAttribute(gemm_i8<2>, cudaFuncAttributeMaxDynamicSharedMemorySize, SM_TOTAL);

#define SYM(p, s) cudaGetSymbolAddress((void**)&p, s)
    int8_t *Wd1T, *mWd1T, *Wg1T, *mWg1T, *Wg2T, *Wd2T, *mWg2T, *mWd2T;
    int8_t *Aq, *Ak, *pqq, *pkq, *ghq, *hidq, *qdmq, *mtq;
    float *poolq, *poolk, *gh, *hid, *part, *Spart;
    unsigned *cmax;
    float *sWd1, *smWd1, *sWg1, *smWg1, *sWg2, *sWd2, *smWg2, *smWd2;
    float *sAq, *sAk, *spq, *spk, *sgh, *shid;
    float *qg, *kg, *qd, *kd, *pos, *lg, *ld;
    SYM(Wd1T, g_Wd1T); SYM(mWd1T, g_mWd1T); SYM(Wg1T, g_Wg1T); SYM(mWg1T, g_mWg1T);
    SYM(Wg2T, g_Wg2T); SYM(Wd2T, g_Wd2T); SYM(mWg2T, g_mWg2T); SYM(mWd2T, g_mWd2T);
    SYM(Aq, g_Aq); SYM(Ak, g_Ak); SYM(pqq, g_pqq); SYM(pkq, g_pkq);
    SYM(ghq, g_ghq); SYM(hidq, g_hidq); SYM(qdmq, g_qdmq); SYM(mtq, g_mtq);
    SYM(poolq, g_poolq); SYM(poolk, g_poolk); SYM(gh, g_gh); SYM(hid, g_hid);
    SYM(part, g_part); SYM(Spart, g_Spart); SYM(cmax, g_cmax);
    SYM(sWd1, g_sWd1); SYM(smWd1, g_smWd1); SYM(sWg1, g_sWg1); SYM(smWg1, g_smWg1);
    SYM(sWg2, g_sWg2); SYM(sWd2, g_sWd2); SYM(smWg2, g_smWg2); SYM(smWd2, g_smWd2);
    SYM(sAq, g_sAq); SYM(sAk, g_sAk); SYM(spq, g_spq); SYM(spk, g_spk);
    SYM(sgh, g_sgh); SYM(shid, g_shid);
    SYM(qg, g_qg); SYM(kg, g_kg); SYM(qd, g_qd); SYM(kd, g_kd);
    SYM(pos, g_pos); SYM(lg, g_lg); SYM(ld, g_ld);
#undef SYM

    // ---- pre-pass: parallel colmax (zero -> partial atomicMax -> finalize) ----
    const int NCM = 4*Dh + 4*De;
    zero_u32<<<(NCM + 255)/256, 256>>>(cmax, NCM);
    unsigned *cWd1 = cmax, *cmWd1 = cmax + Dh, *cWg1 = cmax + 2*Dh, *cmWg1 = cmax + 3*Dh;
    unsigned *cWg2 = cmax + 4*Dh, *cWd2 = cWg2 + De, *cmWg2 = cWg2 + 2*De, *cmWd2 = cWg2 + 3*De;
    colmax_part<<<dim3(Dh/256, Cc/128), 256>>>(Wd1,  cWd1,  Cc, Dh);
    colmax_part<<<dim3(Dh/256, Cc/128), 256>>>(mWd1, cmWd1, Cc, Dh);
    colmax_part<<<dim3(Dh/256, Cc/128), 256>>>(Wg1,  cWg1,  Cc, Dh);
    colmax_part<<<dim3(Dh/256, Cc/128), 256>>>(mWg1, cmWg1, Cc, Dh);
    colmax_part<<<dim3(1, Dh/128), 256>>>(Wg2,  cWg2,  Dh, De);
    colmax_part<<<dim3(1, Dh/128), 256>>>(Wd2,  cWd2,  Dh, De);
    colmax_part<<<dim3(1, Dh/128), 256>>>(mWg2, cmWg2, Dh, De);
    colmax_part<<<dim3(1, Dh/128), 256>>>(mWd2, cmWd2, Dh, De);
    colmax_fin<<<Dh/256, 256>>>(cWd1,  sWd1,  Dh);
    colmax_fin<<<Dh/256, 256>>>(cmWd1, smWd1, Dh);
    colmax_fin<<<Dh/256, 256>>>(cWg1,  sWg1,  Dh);
    colmax_fin<<<Dh/256, 256>>>(cmWg1, smWg1, Dh);
    colmax_fin<<<1, 256>>>(cWg2,  sWg2,  De);
    colmax_fin<<<1, 256>>>(cWd2,  sWd2,  De);
    colmax_fin<<<1, 256>>>(cmWg2, smWg2, De);
    colmax_fin<<<1, 256>>>(cmWd2, smWd2, De);

    dim3 tb(32, 8);
    transpose_quant<<<dim3(Dh/32, Cc/64), tb>>>(Wd1,  sWd1,  Wd1T,  Cc, Dh);
    transpose_quant<<<dim3(Dh/32, Cc/64), tb>>>(mWd1, smWd1, mWd1T, Cc, Dh);
    transpose_quant<<<dim3(Dh/32, Cc/64), tb>>>(Wg1,  sWg1,  Wg1T,  Cc, Dh);
    transpose_quant<<<dim3(Dh/32, Cc/64), tb>>>(mWg1, smWg1, mWg1T, Cc, Dh);
    transpose_quant<<<dim3(De/32, Dh/64), tb>>>(Wg2,  sWg2,  Wg2T,  Dh, De);
    transpose_quant<<<dim3(De/32, Dh/64), tb>>>(Wd2,  sWd2,  Wd2T,  Dh, De);
    transpose_quant<<<dim3(De/32, Dh/64), tb>>>(mWg2, smWg2, mWg2T, Dh, De);
    transpose_quant<<<dim3(De/32, Dh/64), tb>>>(mWd2, smWd2, mWd2T, Dh, De);

    quant_rows<<<Nrow, 256>>>(feat_q, Aq, sAq);
    quant_rows<<<Nrow, 256>>>(feat_k, Ak, sAk);
    pool_kernel<<<dim3(Cc/256, Bn), 256>>>(feat_q, poolq);
    pool_kernel<<<dim3(Cc/256, Bn), 256>>>(feat_k, poolk);
    quant_rows<<<Bn, 256>>>(poolq, pqq, spq);
    quant_rows<<<Bn, 256>>>(poolk, pkq, spk);

    // ---- global head L1 (merged q+k, split-K 4): [128,2048]x[2048,2048] ----
    gemm_i8<0><<<dim3(Dh/64, 1, 8), 256, SM_TOTAL>>>(pqq, pkq, Wg1T, mWg1T,
        spq, spk, sWg1, smWg1, nullptr, nullptr, part,
        Bn, Dh, 2*Cc, 2*Cc, Cc, Cc, 8, 0, 4);
    reduce_split<1><<<(Bn*Dh/4 + 255)/256, 256>>>(part, bg1, gh, 4, (size_t)Bn*Dh, Dh);
    reduce_split<1><<<(Bn*Dh/4 + 255)/256, 256>>>(part + 4*(size_t)Bn*Dh, mbg1,
        gh + (size_t)Bn*Dh, 4, (size_t)Bn*Dh, Dh);
    quant_rows<<<2*Bn, 256>>>(gh, ghq, sgh);

    // ---- global head L2 (merged, split-K 16) ----
    gemm_i8<0><<<dim3(De/64, 1, 32), 256, SM_TOTAL>>>(ghq, ghq + (size_t)Bn*2*Dh,
        Wg2T, mWg2T, sgh, sgh + Bn, sWg2, smWg2, nullptr, nullptr, part,
        Bn, De, 2*Dh, 2*Dh, Dh, Dh, 2, 0, 16);
    reduce_split<0><<<(Bn*De/4 + 255)/256, 256>>>(part, bg2, qg, 16, (size_t)Bn*De, De);
    reduce_split<0><<<(Bn*De/4 + 255)/256, 256>>>(part + 16*(size_t)Bn*De, mbg2, kg,
        16, (size_t)Bn*De, De);

    l2norm_kernel<<<(Bn + 7)/8, dim3(32, 8)>>>(qg, Bn);
    l2norm_kernel<<<(Bn + 7)/8, dim3(32, 8)>>>(kg, Bn);
    lg_kernel<<<Bn, 128>>>(qg, kg, lg);

    // ---- dense head L1 (merged q+k) ----
    gemm_i8<1><<<dim3(Dh/64, Nrow/128, 2), 256, SM_TOTAL>>>(Aq, Ak, Wd1T, mWd1T,
        sAq, sAk, sWd1, smWd1, bd1, mbd1, hid,
        Nrow, Dh, 2*Cc, 2*Cc, Cc, Cc, 32, 0, 1);
    quant_rows<<<2*Nrow, 256>>>(hid, hidq, shid);

    // ---- dense head L2 (merged, uneven split-K 3: 11+11+10 chunks) ----
    gemm_i8<0><<<dim3(De/64, Nrow/128, 6), 256, SM_TOTAL>>>(hidq,
        hidq + (size_t)Nrow*2*Dh, Wd2T, mWd2T, shid, shid + Nrow, sWd2, smWd2,
        nullptr, nullptr, part, Nrow, De, 2*Dh, 2*Dh, Dh, Dh, 10, 2, 3);
    reduce_split<0><<<(Nrow*De/4 + 255)/256, 256>>>(part, bd2, qd, 3, (size_t)Nrow*De, De);
    reduce_split<0><<<(Nrow*De/4 + 255)/256, 256>>>(part + 3*(size_t)Nrow*De, mbd2, kd,
        3, (size_t)Nrow*De, De);

    l2norm_quant<<<Nrow/8, dim3(32, 8)>>>(qd, qdmq, Nrow);
    l2norm_kernel<<<Nrow/8, dim3(32, 8)>>>(kd, Nrow);

    // ---- matching + dense InfoNCE (fused exp epilogue, fixed 1/127 scales) ----
    match_quant<<<Nrow, 128>>>(qd, kd, mtq, pos);
    gemm_i8<2><<<dim3(NPART, Nrow/128, 1), 256, SM_TOTAL>>>(qdmq, qdmq, mtq, mtq,
        nullptr, nullptr, nullptr, nullptr, nullptr, nullptr, Spart,
        Nrow, Nrow, 2*De, 2*De, De, De, 2, 0, 1);
    lse_finish<<<(Nrow + 255)/256, 256>>>(Spart, pos, ld);

    final_kernel<<<1, 256>>>(lg, ld, out);
}

// round 9
// speedup vs baseline: 4.0090x; 3.1228x over previous
#include <cuda_runtime.h>
#include <cuda_bf16.h>
#include <math.h>
#include <stdint.h>

#define Bn   128
#define HW   49
#define Cc   2048
#define Dh   2048
#define De   128
#define Nrow (Bn*HW)          // 6272
#define NTILE 49              // Nrow/128
#define INV_TAU 5.0f

typedef __nv_bfloat16 bf16;

// ========================= PTX helpers =======================================
__device__ __forceinline__ uint32_t smem_u32(const void* p) {
    uint32_t a;
    asm("{ .reg .u64 t; cvta.to.shared.u64 t, %1; cvt.u32.u64 %0, t; }" : "=r"(a) : "l"(p));
    return a;
}
__device__ __forceinline__ void cp16(uint32_t dst, const void* src) {
    asm volatile("cp.async.cg.shared.global [%0], [%1], 16;" :: "r"(dst), "l"(src));
}
#define CP_COMMIT() asm volatile("cp.async.commit_group;" ::: "memory")
#define CP_WAIT0()  asm volatile("cp.async.wait_group 0;" ::: "memory")
#define LDMX4(r0, r1, r2, r3, addr)                                            \
    asm volatile("ldmatrix.sync.aligned.m8n8.x4.shared.b16 {%0,%1,%2,%3}, [%4];" \
        : "=r"(r0), "=r"(r1), "=r"(r2), "=r"(r3) : "r"(addr))

__device__ __forceinline__ void mma16816(float* c, const uint32_t* a, const uint32_t* b) {
    asm volatile("mma.sync.aligned.m16n8k16.row.col.f32.bf16.bf16.f32 "
        "{%0,%1,%2,%3}, {%4,%5,%6,%7}, {%8,%9}, {%0,%1,%2,%3};"
        : "+f"(c[0]), "+f"(c[1]), "+f"(c[2]), "+f"(c[3])
        : "r"(a[0]), "r"(a[1]), "r"(a[2]), "r"(a[3]), "r"(b[0]), "r"(b[1]));
}

// ========================= scratch buffers ===================================
// Weights (B operand): interleaved hi|lo, row stride 2K, lo at +K.
// Activations (A operand): plain bf16 hi only, row stride K.
__device__ __align__(256) bf16 g_Wd1T[(size_t)Dh*2*Cc];
__device__ __align__(256) bf16 g_mWd1T[(size_t)Dh*2*Cc];
__device__ __align__(256) bf16 g_Wg1T[(size_t)Dh*2*Cc];
__device__ __align__(256) bf16 g_mWg1T[(size_t)Dh*2*Cc];
__device__ __align__(256) bf16 g_Wg2T[De*2*Dh], g_Wd2T[De*2*Dh];
__device__ __align__(256) bf16 g_mWg2T[De*2*Dh], g_mWd2T[De*2*Dh];
__device__ __align__(256) bf16 g_Aq[(size_t)Nrow*Cc], g_Ak[(size_t)Nrow*Cc];
__device__ __align__(256) bf16 g_pq[Bn*Cc], g_pk[Bn*Cc];
__device__ __align__(256) bf16 g_gh[2*(size_t)Bn*Dh];
__device__ __align__(256) bf16 g_hid[2*(size_t)Nrow*Dh];
__device__ __align__(256) bf16 g_qdm[Nrow*De];
__device__ __align__(256) bf16 g_mt[Nrow*2*De];                  // interleaved
__device__ __align__(256) float g_part[16*(size_t)Bn*Dh > 6*(size_t)Nrow*De ?
                                       16*(size_t)Bn*Dh : 6*(size_t)Nrow*De];
__device__ __align__(256) float g_Spart[(size_t)NTILE*Nrow];
__device__ float g_qg[Bn*De], g_kg[Bn*De];
__device__ float g_qd[Nrow*De], g_kd[Nrow*De];
__device__ float g_pos[Nrow], g_lg[Bn], g_ld[Nrow];

// ========================= pre-pass kernels ==================================
// transpose + split: W[K][N] fp32 -> T[n][2K] interleaved hi|lo.
__global__ void transpose_split(const float* __restrict__ W, bf16* __restrict__ T,
                                int K, int N) {
    __shared__ float t[32][65];
    int n0 = blockIdx.x * 32, k0 = blockIdx.y * 64;
    int tx = threadIdx.x, ty = threadIdx.y;
#pragma unroll
    for (int r = 0; r < 64; r += 8)
        t[tx][r + ty] = W[(size_t)(k0 + r + ty) * N + n0 + tx];
    __syncthreads();
#pragma unroll
    for (int j = 0; j < 4; j++) {
        int nl = ty + j * 8;
        float v0 = t[nl][2 * tx], v1 = t[nl][2 * tx + 1];
        bf16 h0 = __float2bfloat16(v0), h1 = __float2bfloat16(v1);
        size_t o = (size_t)(n0 + nl) * (2 * K) + k0 + 2 * tx;
        __nv_bfloat162 ph; ph.x = h0; ph.y = h1;
        *(__nv_bfloat162*)&T[o] = ph;
        __nv_bfloat162 pl;
        pl.x = __float2bfloat16(v0 - __bfloat162float(h0));
        pl.y = __float2bfloat16(v1 - __bfloat162float(h1));
        *(__nv_bfloat162*)&T[o + K] = pl;
    }
}

// fused: per-pixel bf16 convert (hi only) + mean-pool bf16 (hi only)
__global__ void feat_prep(const float* __restrict__ f, bf16* __restrict__ A,
                          bf16* __restrict__ pool) {
    int b = blockIdx.y;
    int c = blockIdx.x * 256 + threadIdx.x;
    const float* p = f + (size_t)b * HW * Cc + c;
    float s = 0.f;
#pragma unroll
    for (int i = 0; i < HW; i++) {
        float v = p[(size_t)i * Cc];
        s += v;
        A[((size_t)b * HW + i) * Cc + c] = __float2bfloat16(v);
    }
    pool[(size_t)b * Cc + c] = __float2bfloat16(s * (1.0f / 49.0f));
}

// ========================= 2-pass mma.sync GEMM ==============================
// D[m][n] = sum_k A[m][k]*B[n][k];  A plain bf16 (ldA), B interleaved hi|lo
// (ldB = 2K row stride, lo at +loB).  2 passes: Ah*Bh + Ah*Bl.
// 128x128 tile, BK=32, cp.async double buffer, ldmatrix fragments.
// grid.z = head*nzk + kidx; uneven split-K via (nbC, remC).
// EPI 0: fp32 partial at Cf + z*M*N
// EPI 1: bias+relu -> plain bf16 at Cb + head*M*N
// EPI 2: exp-rowsum -> Cf[blockIdx.x*M + row]
#define ROWB 80
#define MATB (128*ROWB)         // 10240
#define STGB (3*MATB)           // 30720
#define SM_TOTAL (2*STGB)       // 61440

template<int EPI>
__global__ __launch_bounds__(256, 2)
void gemm_mma(const bf16* __restrict__ A0, const bf16* __restrict__ A1,
              const bf16* __restrict__ B0, const bf16* __restrict__ B1,
              const float* __restrict__ bias0, const float* __restrict__ bias1,
              float* __restrict__ Cf, bf16* __restrict__ Cb,
              int M, int N, int ldA, int ldB, int loB,
              int nbC, int remC, int nzk) {
    extern __shared__ char smem[];
    const uint32_t sb = smem_u32(smem);
    const int tid = threadIdx.x;
    const int wid = tid >> 5;
    const int lid = tid & 31;
    const int wm = wid >> 2;          // 0..1 (64 rows)
    const int wn = wid & 3;           // 0..3 (32 cols)
    const int g = lid >> 2;
    const int t = lid & 3;
    const int bm = blockIdx.y * 128;
    const int bn = blockIdx.x * 128;
    const int z = blockIdx.z;
    const int head = z / nzk;
    const int kidx = z - head * nzk;
    const int kbeg = (kidx * nbC + min(kidx, remC)) * 32;
    const int nch = nbC + (kidx < remC ? 1 : 0);

    const bf16* A = (head ? A1 : A0) + (size_t)bm * ldA + kbeg;
    const bf16* B = (head ? B1 : B0) + (size_t)bn * ldB + kbeg;
    const float* bias = head ? bias1 : bias0;

    const int r0 = tid >> 2, c0 = tid & 3;

    float acc[4][4][4];
#pragma unroll
    for (int i = 0; i < 4; i++)
#pragma unroll
        for (int j = 0; j < 4; j++)
#pragma unroll
            for (int c = 0; c < 4; c++) acc[i][j][c] = 0.f;

    // prologue: chunk 0 -> stage 0
#pragma unroll
    for (int s = 0; s < 2; s++) {
        int r = r0 + s * 64;
        cp16(sb + 0*MATB + r*ROWB + c0*16, A + (size_t)r * ldA + c0 * 8);
        const bf16* pb = B + (size_t)r * ldB + c0 * 8;
        cp16(sb + 1*MATB + r*ROWB + c0*16, pb);
        cp16(sb + 2*MATB + r*ROWB + c0*16, pb + loB);
    }
    CP_COMMIT();

    const uint32_t a_lm = (uint32_t)((wm*64 + (lid & 7) + ((lid >> 3) & 1) * 8) * ROWB
                                     + ((lid >> 4) & 1) * 16);
    const uint32_t b_lm = (uint32_t)((wn*32 + (lid & 7) + ((lid >> 4) & 1) * 8) * ROWB
                                     + ((lid >> 3) & 1) * 16);

    for (int ch = 0; ch < nch; ch++) {
        CP_WAIT0();
        __syncthreads();
        if (ch + 1 < nch) {
            const int k0 = (ch + 1) * 32;
            uint32_t st = sb + ((ch + 1) & 1) * STGB;
#pragma unroll
            for (int s = 0; s < 2; s++) {
                int r = r0 + s * 64;
                cp16(st + 0*MATB + r*ROWB + c0*16, A + (size_t)r * ldA + k0 + c0 * 8);
                const bf16* pb = B + (size_t)r * ldB + k0 + c0 * 8;
                cp16(st + 1*MATB + r*ROWB + c0*16, pb);
                cp16(st + 2*MATB + r*ROWB + c0*16, pb + loB);
            }
            CP_COMMIT();
        }
        const uint32_t st = sb + (ch & 1) * STGB;
#pragma unroll
        for (int ks = 0; ks < 2; ks++) {
            uint32_t ah[4][4];
#pragma unroll
            for (int i = 0; i < 4; i++) {
                uint32_t aa = st + a_lm + i * (16 * ROWB) + ks * 32;
                LDMX4(ah[i][0], ah[i][1], ah[i][2], ah[i][3], aa);
            }
#pragma unroll
            for (int jp = 0; jp < 2; jp++) {
                uint32_t bh[2][2], bl[2][2];
                uint32_t bb = st + 1*MATB + b_lm + jp * (16 * ROWB) + ks * 32;
                LDMX4(bh[0][0], bh[0][1], bh[1][0], bh[1][1], bb);
                LDMX4(bl[0][0], bl[0][1], bl[1][0], bl[1][1], bb + MATB);
#pragma unroll
                for (int i = 0; i < 4; i++)
#pragma unroll
                    for (int jj = 0; jj < 2; jj++) {
                        float* a = acc[i][jp*2 + jj];
                        mma16816(a, ah[i], bh[jj]);
                        mma16816(a, ah[i], bl[jj]);
                    }
            }
        }
        __syncthreads();
    }

    // ---- epilogue ----
    if (EPI == 2) {
        float rs[8];
#pragma unroll
        for (int i = 0; i < 4; i++)
#pragma unroll
            for (int h = 0; h < 2; h++) {
                float s = 0.f;
#pragma unroll
                for (int j = 0; j < 4; j++)
                    s += __expf(acc[i][j][2*h] * INV_TAU)
                       + __expf(acc[i][j][2*h + 1] * INV_TAU);
                s += __shfl_xor_sync(0xFFFFFFFFu, s, 1);
                s += __shfl_xor_sync(0xFFFFFFFFu, s, 2);
                rs[i*2 + h] = s;
            }
        float* sm = (float*)smem;
        __syncthreads();
        if (t == 0) {
#pragma unroll
            for (int idx = 0; idx < 8; idx++) {
                int i = idx >> 1, h = idx & 1;
                int row = wm*64 + i*16 + g + h*8;
                sm[row*4 + wn] = rs[idx];
            }
        }
        __syncthreads();
        if (tid < 128) {
            float tot = sm[tid*4+0] + sm[tid*4+1] + sm[tid*4+2] + sm[tid*4+3];
            Cf[(size_t)blockIdx.x * M + bm + tid] = tot;
        }
        return;
    }
#pragma unroll
    for (int i = 0; i < 4; i++) {
        int row0 = bm + wm*64 + i*16 + g;
#pragma unroll
        for (int j = 0; j < 4; j++) {
            int col = bn + wn*32 + j*8 + 2*t;
            float b0 = 0.f, b1 = 0.f;
            if (bias) { b0 = bias[col]; b1 = bias[col + 1]; }
#pragma unroll
            for (int h = 0; h < 2; h++) {
                int row = row0 + h*8;
                float v0 = acc[i][j][2*h]     + b0;
                float v1 = acc[i][j][2*h + 1] + b1;
                if (EPI == 1) {
                    v0 = fmaxf(v0, 0.f); v1 = fmaxf(v1, 0.f);
                    __nv_bfloat162 ph;
                    ph.x = __float2bfloat16(v0); ph.y = __float2bfloat16(v1);
                    *(__nv_bfloat162*)&Cb[(size_t)head * M * N + (size_t)row * N + col] = ph;
                } else {
                    size_t o = (size_t)z * M * N + (size_t)row * N + col;
                    float2 fv; fv.x = v0; fv.y = v1;
                    *(float2*)&Cf[o] = fv;
                }
            }
        }
    }
}

// split-K reduce. EPI 0: fp32+bias -> Cf. EPI 1: bias+relu -> plain bf16 Cb.
template<int EPI>
__global__ void reduce_split(const float* __restrict__ part, const float* __restrict__ bias,
                             float* __restrict__ Cf, bf16* __restrict__ Cb,
                             int S, size_t MN, int N) {
    size_t i4 = (size_t)blockIdx.x * 256 + threadIdx.x;
    if (i4 * 4 >= MN) return;
    float4 a = {0.f, 0.f, 0.f, 0.f};
    for (int s = 0; s < S; s++) {
        float4 v = *(const float4*)(part + s * MN + i4 * 4);
        a.x += v.x; a.y += v.y; a.z += v.z; a.w += v.w;
    }
    size_t base = i4 * 4;
    int n = (int)(base % N);
    a.x += bias[n]; a.y += bias[n+1]; a.z += bias[n+2]; a.w += bias[n+3];
    if (EPI == 1) {
        a.x = fmaxf(a.x, 0.f); a.y = fmaxf(a.y, 0.f);
        a.z = fmaxf(a.z, 0.f); a.w = fmaxf(a.w, 0.f);
        __nv_bfloat162 p0, p1;
        p0.x = __float2bfloat16(a.x); p0.y = __float2bfloat16(a.y);
        p1.x = __float2bfloat16(a.z); p1.y = __float2bfloat16(a.w);
        *(__nv_bfloat162*)&Cb[base]     = p0;
        *(__nv_bfloat162*)&Cb[base + 2] = p1;
    } else {
        *(float4*)&Cf[base] = a;
    }
}

// ========================= small kernels =====================================
__global__ void l2norm_kernel(float* __restrict__ x, int rows) {
    int row = blockIdx.x * 8 + threadIdx.y;
    if (row >= rows) return;
    float* p = x + (size_t)row * De;
    int lane = threadIdx.x;
    float4 v = *(float4*)(p + lane * 4);
    float ss = v.x*v.x + v.y*v.y + v.z*v.z + v.w*v.w;
#pragma unroll
    for (int o = 16; o; o >>= 1) ss += __shfl_xor_sync(0xFFFFFFFFu, ss, o);
    float r = 1.0f / sqrtf(fmaxf(ss, 1e-12f));
    v.x *= r; v.y *= r; v.z *= r; v.w *= r;
    *(float4*)(p + lane * 4) = v;
}

// l2norm + plain bf16 copy
__global__ void l2norm_bf16(float* __restrict__ x, bf16* __restrict__ m, int rows) {
    int row = blockIdx.x * 8 + threadIdx.y;
    if (row >= rows) return;
    float* p = x + (size_t)row * De;
    int lane = threadIdx.x;
    float4 v = *(float4*)(p + lane * 4);
    float ss = v.x*v.x + v.y*v.y + v.z*v.z + v.w*v.w;
#pragma unroll
    for (int o = 16; o; o >>= 1) ss += __shfl_xor_sync(0xFFFFFFFFu, ss, o);
    float r = 1.0f / sqrtf(fmaxf(ss, 1e-12f));
    v.x *= r; v.y *= r; v.z *= r; v.w *= r;
    *(float4*)(p + lane * 4) = v;
    size_t o = (size_t)row * De + lane * 4;
    __nv_bfloat162 p0, p1;
    p0.x = __float2bfloat16(v.x); p0.y = __float2bfloat16(v.y);
    p1.x = __float2bfloat16(v.z); p1.y = __float2bfloat16(v.w);
    *(__nv_bfloat162*)&m[o]     = p0;
    *(__nv_bfloat162*)&m[o + 2] = p1;
}

__global__ void lg_kernel(const float* __restrict__ qg, const float* __restrict__ kg,
                          float* __restrict__ out) {
    int row = blockIdx.x;
    __shared__ float qs[De];
    __shared__ float red[128];
    int t = threadIdx.x;
    qs[t] = qg[(size_t)row * De + t];
    __syncthreads();
    const float* kp = kg + (size_t)t * De;
    float dot = 0.f;
#pragma unroll 8
    for (int c = 0; c < De; c++) dot = fmaf(qs[c], kp[c], dot);
    float logit = dot * INV_TAU;          // |logit| <= 5
    red[t] = __expf(logit); __syncthreads();
    for (int s = 64; s; s >>= 1) { if (t < s) red[t] += red[t + s]; __syncthreads(); }
    float lse = logf(red[0]);
    if (t == row) out[row] = lse - logit;
}

// argmax match; writes matched rows as interleaved bf16 hi|lo (B operand)
__global__ void match_kernel(const float* __restrict__ qd, const float* __restrict__ kd,
                             bf16* __restrict__ mt, float* __restrict__ pos) {
    int row = blockIdx.x;
    int b = row / HW;
    __shared__ float qs[De];
    __shared__ float dots[64];
    __shared__ int   s_idx;
    __shared__ float s_val;
    int t = threadIdx.x;
    qs[t] = qd[(size_t)row * De + t];
    __syncthreads();
    if (t < HW) {
        const float* kp = kd + (size_t)(b * HW + t) * De;
        float d = 0.f;
#pragma unroll 8
        for (int c = 0; c < De; c++) d = fmaf(qs[c], kp[c], d);
        dots[t] = d;
    }
    __syncthreads();
    if (t == 0) {
        float bv = dots[0]; int bi = 0;
        for (int j = 1; j < HW; j++)
            if (dots[j] > bv) { bv = dots[j]; bi = j; }
        s_idx = bi; s_val = bv;
    }
    __syncthreads();
    float v = kd[(size_t)(b * HW + s_idx) * De + t];
    bf16 h = __float2bfloat16(v);
    size_t o = (size_t)row * (2 * De) + t;
    mt[o]      = h;
    mt[o + De] = __float2bfloat16(v - __bfloat162float(h));
    if (t == 0) pos[row] = s_val;
}

__global__ void lse_finish(const float* __restrict__ Spart, const float* __restrict__ pos,
                           float* __restrict__ out) {
    int row = blockIdx.x * 256 + threadIdx.x;
    if (row >= Nrow) return;
    float s = 0.f;
#pragma unroll
    for (int j = 0; j < NTILE; j++) s += Spart[(size_t)j * Nrow + row];
    out[row] = logf(s) - pos[row] * INV_TAU;
}

__global__ void final_kernel(const float* __restrict__ lg, const float* __restrict__ ld,
                             float* __restrict__ out) {
    int t = threadIdx.x;
    float s1 = 0.f, s2 = 0.f;
    if (t < Bn) s1 = lg[t];
    for (int j = t; j < Nrow; j += 256) s2 += ld[j];
    __shared__ float r1[256], r2[256];
    r1[t] = s1; r2[t] = s2; __syncthreads();
    for (int o = 128; o; o >>= 1) {
        if (t < o) { r1[t] += r1[t + o]; r2[t] += r2[t + o]; }
        __syncthreads();
    }
    if (t == 0) out[0] = 0.5f * (r1[0] / (float)Bn) + 0.5f * (r2[0] / (float)Nrow);
}

// ========================= host orchestration ================================
extern "C" void kernel_launch(void* const* d_in, const int* in_sizes, int n_in,
                              void* d_out, int out_size) {
    const float* feat_q = (const float*)d_in[0];
    const float* feat_k = (const float*)d_in[1];
    const float* Wg1  = (const float*)d_in[2];   const float* bg1 = (const float*)d_in[3];
    const float* Wg2  = (const float*)d_in[4];   const float* bg2 = (const float*)d_in[5];
    const float* Wd1  = (const float*)d_in[6];   const float* bd1 = (const float*)d_in[7];
    const float* Wd2  = (const float*)d_in[8];   const float* bd2 = (const float*)d_in[9];
    const float* mWg1 = (const float*)d_in[10];  const float* mbg1 = (const float*)d_in[11];
    const float* mWg2 = (const float*)d_in[12];  const float* mbg2 = (const float*)d_in[13];
    const float* mWd1 = (const float*)d_in[14];  const float* mbd1 = (const float*)d_in[15];
    const float* mWd2 = (const float*)d_in[16];  const float* mbd2 = (const float*)d_in[17];
    float* out = (float*)d_out;

    cudaFuncSetAttribute(gemm_mma<0>, cudaFuncAttributeMaxDynamicSharedMemorySize, SM_TOTAL);
    cudaFuncSetAttribute(gemm_mma<1>, cudaFuncAttributeMaxDynamicSharedMemorySize, SM_TOTAL);
    cudaFuncSetAttribute(gemm_mma<2>, cudaFuncAttributeMaxDynamicSharedMemorySize, SM_TOTAL);

#define SYM(p, s) cudaGetSymbolAddress((void**)&p, s)
    bf16 *Wd1T, *mWd1T, *Wg1T, *mWg1T, *Wg2T, *Wd2T, *mWg2T, *mWd2T;
    bf16 *Aq, *Ak, *pq, *pk, *gh, *hid, *qdm, *mt;
    float *part, *Spart, *qg, *kg, *qd, *kd, *pos, *lg, *ld;
    SYM(Wd1T, g_Wd1T); SYM(mWd1T, g_mWd1T); SYM(Wg1T, g_Wg1T); SYM(mWg1T, g_mWg1T);
    SYM(Wg2T, g_Wg2T); SYM(Wd2T, g_Wd2T); SYM(mWg2T, g_mWg2T); SYM(mWd2T, g_mWd2T);
    SYM(Aq, g_Aq); SYM(Ak, g_Ak); SYM(pq, g_pq); SYM(pk, g_pk);
    SYM(gh, g_gh); SYM(hid, g_hid); SYM(qdm, g_qdm); SYM(mt, g_mt);
    SYM(part, g_part); SYM(Spart, g_Spart);
    SYM(qg, g_qg); SYM(kg, g_kg); SYM(qd, g_qd); SYM(kd, g_kd);
    SYM(pos, g_pos); SYM(lg, g_lg); SYM(ld, g_ld);
#undef SYM

    // ---- pre-pass ----
    dim3 tb(32, 8);
    transpose_split<<<dim3(Dh/32, Cc/64), tb>>>(Wd1,  Wd1T,  Cc, Dh);
    transpose_split<<<dim3(Dh/32, Cc/64), tb>>>(mWd1, mWd1T, Cc, Dh);
    transpose_split<<<dim3(Dh/32, Cc/64), tb>>>(Wg1,  Wg1T,  Cc, Dh);
    transpose_split<<<dim3(Dh/32, Cc/64), tb>>>(mWg1, mWg1T, Cc, Dh);
    transpose_split<<<dim3(De/32, Dh/64), tb>>>(Wg2,  Wg2T,  Dh, De);
    transpose_split<<<dim3(De/32, Dh/64), tb>>>(Wd2,  Wd2T,  Dh, De);
    transpose_split<<<dim3(De/32, Dh/64), tb>>>(mWg2, mWg2T, Dh, De);
    transpose_split<<<dim3(De/32, Dh/64), tb>>>(mWd2, mWd2T, Dh, De);

    feat_prep<<<dim3(Cc/256, Bn), 256>>>(feat_q, Aq, pq);
    feat_prep<<<dim3(Cc/256, Bn), 256>>>(feat_k, Ak, pk);

    // ---- global head L1 (q+k merged, split-K 8) ----
    gemm_mma<0><<<dim3(Dh/128, 1, 16), 256, SM_TOTAL>>>(pq, pk, Wg1T, mWg1T,
        nullptr, nullptr, part, nullptr, Bn, Dh, Cc, 2*Cc, Cc, 8, 0, 8);
    reduce_split<1><<<(Bn*Dh/4 + 255)/256, 256>>>(part, bg1, nullptr, gh, 8, (size_t)Bn*Dh, Dh);
    reduce_split<1><<<(Bn*Dh/4 + 255)/256, 256>>>(part + 8*(size_t)Bn*Dh, mbg1, nullptr,
        gh + (size_t)Bn*Dh, 8, (size_t)Bn*Dh, Dh);
    // ---- global head L2 (merged, split-K 16) ----
    gemm_mma<0><<<dim3(1, 1, 32), 256, SM_TOTAL>>>(gh, gh + (size_t)Bn*Dh, Wg2T, mWg2T,
        nullptr, nullptr, part, nullptr, Bn, De, Dh, 2*Dh, Dh, 4, 0, 16);
    reduce_split<0><<<(Bn*De/4 + 255)/256, 256>>>(part, bg2, qg, nullptr, 16, (size_t)Bn*De, De);
    reduce_split<0><<<(Bn*De/4 + 255)/256, 256>>>(part + 16*(size_t)Bn*De, mbg2, kg, nullptr,
        16, (size_t)Bn*De, De);

    l2norm_kernel<<<(Bn + 7)/8, dim3(32, 8)>>>(qg, Bn);
    l2norm_kernel<<<(Bn + 7)/8, dim3(32, 8)>>>(kg, Bn);
    lg_kernel<<<Bn, 128>>>(qg, kg, lg);

    // ---- dense head L1 (q+k merged) ----
    gemm_mma<1><<<dim3(Dh/128, NTILE, 2), 256, SM_TOTAL>>>(Aq, Ak, Wd1T, mWd1T,
        bd1, mbd1, nullptr, hid, Nrow, Dh, Cc, 2*Cc, Cc, 64, 0, 1);
    // ---- dense head L2 (merged, uneven split-K 3 -> 294 CTAs = 1 wave) ----
    gemm_mma<0><<<dim3(1, NTILE, 6), 256, SM_TOTAL>>>(hid, hid + (size_t)Nrow*Dh,
        Wd2T, mWd2T, nullptr, nullptr, part, nullptr, Nrow, De, Dh, 2*Dh, Dh, 21, 1, 3);
    reduce_split<0><<<(Nrow*De/4 + 255)/256, 256>>>(part, bd2, qd, nullptr, 3, (size_t)Nrow*De, De);
    reduce_split<0><<<(Nrow*De/4 + 255)/256, 256>>>(part + 3*(size_t)Nrow*De, mbd2, kd, nullptr,
        3, (size_t)Nrow*De, De);

    l2norm_bf16<<<Nrow/8, dim3(32, 8)>>>(qd, qdm, Nrow);
    l2norm_kernel<<<Nrow/8, dim3(32, 8)>>>(kd, Nrow);

    // ---- matching + dense InfoNCE (fused exp epilogue) ----
    match_kernel<<<Nrow, 128>>>(qd, kd, mt, pos);
    gemm_mma<2><<<dim3(NTILE, NTILE, 1), 256, SM_TOTAL>>>(qdm, qdm, mt, mt,
        nullptr, nullptr, Spart, nullptr, Nrow, Nrow, De, 2*De, De, 4, 0, 1);
    lse_finish<<<(Nrow + 255)/256, 256>>>(Spart, pos, ld);

    final_kernel<<<1, 256>>>(lg, ld, out);
}

// round 10
// speedup vs baseline: 5.6502x; 1.4094x over previous
#include <cuda_runtime.h>
#include <cuda_bf16.h>
#include <math.h>
#include <stdint.h>

#define Bn   128
#define HW   49
#define Cc   2048
#define Dh   2048
#define De   128
#define Nrow (Bn*HW)          // 6272
#define NTILE 49              // Nrow/128
#define INV_TAU 5.0f

typedef __nv_bfloat16 bf16;

// ========================= PTX helpers =======================================
__device__ __forceinline__ uint32_t smem_u32(const void* p) {
    uint32_t a;
    asm("{ .reg .u64 t; cvta.to.shared.u64 t, %1; cvt.u32.u64 %0, t; }" : "=r"(a) : "l"(p));
    return a;
}
__device__ __forceinline__ void cp16(uint32_t dst, const void* src) {
    asm volatile("cp.async.cg.shared.global [%0], [%1], 16;" :: "r"(dst), "l"(src));
}
#define CP_COMMIT() asm volatile("cp.async.commit_group;" ::: "memory")
#define CP_WAIT0()  asm volatile("cp.async.wait_group 0;" ::: "memory")
#define LDMX4(r0, r1, r2, r3, addr)                                            \
    asm volatile("ldmatrix.sync.aligned.m8n8.x4.shared.b16 {%0,%1,%2,%3}, [%4];" \
        : "=r"(r0), "=r"(r1), "=r"(r2), "=r"(r3) : "r"(addr))

__device__ __forceinline__ void mma16816(float* c, const uint32_t* a, const uint32_t* b) {
    asm volatile("mma.sync.aligned.m16n8k16.row.col.f32.bf16.bf16.f32 "
        "{%0,%1,%2,%3}, {%4,%5,%6,%7}, {%8,%9}, {%0,%1,%2,%3};"
        : "+f"(c[0]), "+f"(c[1]), "+f"(c[2]), "+f"(c[3])
        : "r"(a[0]), "r"(a[1]), "r"(a[2]), "r"(a[3]), "r"(b[0]), "r"(b[1]));
}

// ========================= scratch buffers ===================================
// All GEMM operands: plain bf16, row stride K.
__device__ __align__(256) bf16 g_Wd1T[(size_t)Dh*Cc];
__device__ __align__(256) bf16 g_mWd1T[(size_t)Dh*Cc];
__device__ __align__(256) bf16 g_Wg1T[(size_t)Dh*Cc];
__device__ __align__(256) bf16 g_mWg1T[(size_t)Dh*Cc];
__device__ __align__(256) bf16 g_Wg2T[De*Dh], g_Wd2T[De*Dh];
__device__ __align__(256) bf16 g_mWg2T[De*Dh], g_mWd2T[De*Dh];
__device__ __align__(256) bf16 g_Aq[(size_t)Nrow*Cc], g_Ak[(size_t)Nrow*Cc];
__device__ __align__(256) bf16 g_pq[Bn*Cc], g_pk[Bn*Cc];
__device__ __align__(256) bf16 g_gh[2*(size_t)Bn*Dh];
__device__ __align__(256) bf16 g_hid[2*(size_t)Nrow*Dh];
__device__ __align__(256) bf16 g_qdm[Nrow*De];
__device__ __align__(256) bf16 g_mt[Nrow*De];
__device__ __align__(256) float g_part[16*(size_t)Bn*Dh > 6*(size_t)Nrow*De ?
                                       16*(size_t)Bn*Dh : 6*(size_t)Nrow*De];
__device__ __align__(256) float g_Spart[(size_t)NTILE*Nrow];
__device__ float g_qg[Bn*De], g_kg[Bn*De];
__device__ float g_qd[Nrow*De], g_kd[Nrow*De];
__device__ float g_pos[Nrow], g_lg[Bn], g_ld[Nrow];

// ========================= pre-pass kernels ==================================
// transpose: W[K][N] fp32 -> T[n][K] plain bf16
__global__ void transpose_bf16(const float* __restrict__ W, bf16* __restrict__ T,
                               int K, int N) {
    __shared__ float t[32][65];
    int n0 = blockIdx.x * 32, k0 = blockIdx.y * 64;
    int tx = threadIdx.x, ty = threadIdx.y;
#pragma unroll
    for (int r = 0; r < 64; r += 8)
        t[tx][r + ty] = W[(size_t)(k0 + r + ty) * N + n0 + tx];
    __syncthreads();
#pragma unroll
    for (int j = 0; j < 4; j++) {
        int nl = ty + j * 8;
        __nv_bfloat162 ph;
        ph.x = __float2bfloat16(t[nl][2 * tx]);
        ph.y = __float2bfloat16(t[nl][2 * tx + 1]);
        *(__nv_bfloat162*)&T[(size_t)(n0 + nl) * K + k0 + 2 * tx] = ph;
    }
}

// fused: per-pixel bf16 convert + mean-pool bf16
__global__ void feat_prep(const float* __restrict__ f, bf16* __restrict__ A,
                          bf16* __restrict__ pool) {
    int b = blockIdx.y;
    int c = blockIdx.x * 256 + threadIdx.x;
    const float* p = f + (size_t)b * HW * Cc + c;
    float s = 0.f;
#pragma unroll
    for (int i = 0; i < HW; i++) {
        float v = p[(size_t)i * Cc];
        s += v;
        A[((size_t)b * HW + i) * Cc + c] = __float2bfloat16(v);
    }
    pool[(size_t)b * Cc + c] = __float2bfloat16(s * (1.0f / 49.0f));
}

// ========================= 1-pass mma.sync GEMM ==============================
// D[m][n] = sum_k A[m][k]*B[n][k]; A,B plain bf16.
// 128x128 tile, BK=32, cp.async double buffer, ldmatrix fragments.
// grid.z = head*nzk + kidx; uneven split-K via (nbC, remC).
// EPI 0: fp32 partial at Cf + z*M*N
// EPI 1: bias+relu -> plain bf16 at Cb + head*M*N
// EPI 2: exp-rowsum -> Cf[blockIdx.x*M + row]
#define ROWB 80
#define MATB (128*ROWB)         // 10240
#define STGB (2*MATB)           // 20480
#define SM_TOTAL (2*STGB)       // 40960

template<int EPI>
__global__ __launch_bounds__(256, 2)
void gemm_mma(const bf16* __restrict__ A0, const bf16* __restrict__ A1,
              const bf16* __restrict__ B0, const bf16* __restrict__ B1,
              const float* __restrict__ bias0, const float* __restrict__ bias1,
              float* __restrict__ Cf, bf16* __restrict__ Cb,
              int M, int N, int ldA, int ldB,
              int nbC, int remC, int nzk) {
    extern __shared__ char smem[];
    const uint32_t sb = smem_u32(smem);
    const int tid = threadIdx.x;
    const int wid = tid >> 5;
    const int lid = tid & 31;
    const int wm = wid >> 2;          // 0..1 (64 rows)
    const int wn = wid & 3;           // 0..3 (32 cols)
    const int g = lid >> 2;
    const int t = lid & 3;
    const int bm = blockIdx.y * 128;
    const int bn = blockIdx.x * 128;
    const int z = blockIdx.z;
    const int head = z / nzk;
    const int kidx = z - head * nzk;
    const int kbeg = (kidx * nbC + min(kidx, remC)) * 32;
    const int nch = nbC + (kidx < remC ? 1 : 0);

    const bf16* A = (head ? A1 : A0) + (size_t)bm * ldA + kbeg;
    const bf16* B = (head ? B1 : B0) + (size_t)bn * ldB + kbeg;
    const float* bias = head ? bias1 : bias0;

    const int r0 = tid >> 2, c0 = tid & 3;

    float acc[4][4][4];
#pragma unroll
    for (int i = 0; i < 4; i++)
#pragma unroll
        for (int j = 0; j < 4; j++)
#pragma unroll
            for (int c = 0; c < 4; c++) acc[i][j][c] = 0.f;

    // prologue: chunk 0 -> stage 0
#pragma unroll
    for (int s = 0; s < 2; s++) {
        int r = r0 + s * 64;
        cp16(sb + 0*MATB + r*ROWB + c0*16, A + (size_t)r * ldA + c0 * 8);
        cp16(sb + 1*MATB + r*ROWB + c0*16, B + (size_t)r * ldB + c0 * 8);
    }
    CP_COMMIT();

    const uint32_t a_lm = (uint32_t)((wm*64 + (lid & 7) + ((lid >> 3) & 1) * 8) * ROWB
                                     + ((lid >> 4) & 1) * 16);
    const uint32_t b_lm = (uint32_t)((wn*32 + (lid & 7) + ((lid >> 4) & 1) * 8) * ROWB
                                     + ((lid >> 3) & 1) * 16);

    for (int ch = 0; ch < nch; ch++) {
        CP_WAIT0();
        __syncthreads();
        if (ch + 1 < nch) {
            const int k0 = (ch + 1) * 32;
            uint32_t st = sb + ((ch + 1) & 1) * STGB;
#pragma unroll
            for (int s = 0; s < 2; s++) {
                int r = r0 + s * 64;
                cp16(st + 0*MATB + r*ROWB + c0*16, A + (size_t)r * ldA + k0 + c0 * 8);
                cp16(st + 1*MATB + r*ROWB + c0*16, B + (size_t)r * ldB + k0 + c0 * 8);
            }
            CP_COMMIT();
        }
        const uint32_t st = sb + (ch & 1) * STGB;
#pragma unroll
        for (int ks = 0; ks < 2; ks++) {
            uint32_t ah[4][4];
#pragma unroll
            for (int i = 0; i < 4; i++) {
                uint32_t aa = st + a_lm + i * (16 * ROWB) + ks * 32;
                LDMX4(ah[i][0], ah[i][1], ah[i][2], ah[i][3], aa);
            }
#pragma unroll
            for (int jp = 0; jp < 2; jp++) {
                uint32_t bh[2][2];
                uint32_t bb = st + 1*MATB + b_lm + jp * (16 * ROWB) + ks * 32;
                LDMX4(bh[0][0], bh[0][1], bh[1][0], bh[1][1], bb);
#pragma unroll
                for (int i = 0; i < 4; i++)
#pragma unroll
                    for (int jj = 0; jj < 2; jj++)
                        mma16816(acc[i][jp*2 + jj], ah[i], bh[jj]);
            }
        }
        __syncthreads();
    }

    // ---- epilogue ----
    if (EPI == 2) {
        float rs[8];
#pragma unroll
        for (int i = 0; i < 4; i++)
#pragma unroll
            for (int h = 0; h < 2; h++) {
                float s = 0.f;
#pragma unroll
                for (int j = 0; j < 4; j++)
                    s += __expf(acc[i][j][2*h] * INV_TAU)
                       + __expf(acc[i][j][2*h + 1] * INV_TAU);
                s += __shfl_xor_sync(0xFFFFFFFFu, s, 1);
                s += __shfl_xor_sync(0xFFFFFFFFu, s, 2);
                rs[i*2 + h] = s;
            }
        float* sm = (float*)smem;
        __syncthreads();
        if (t == 0) {
#pragma unroll
            for (int idx = 0; idx < 8; idx++) {
                int i = idx >> 1, h = idx & 1;
                int row = wm*64 + i*16 + g + h*8;
                sm[row*4 + wn] = rs[idx];
            }
        }
        __syncthreads();
        if (tid < 128) {
            float tot = sm[tid*4+0] + sm[tid*4+1] + sm[tid*4+2] + sm[tid*4+3];
            Cf[(size_t)blockIdx.x * M + bm + tid] = tot;
        }
        return;
    }
#pragma unroll
    for (int i = 0; i < 4; i++) {
        int row0 = bm + wm*64 + i*16 + g;
#pragma unroll
        for (int j = 0; j < 4; j++) {
            int col = bn + wn*32 + j*8 + 2*t;
            float b0 = 0.f, b1 = 0.f;
            if (bias) { b0 = bias[col]; b1 = bias[col + 1]; }
#pragma unroll
            for (int h = 0; h < 2; h++) {
                int row = row0 + h*8;
                float v0 = acc[i][j][2*h]     + b0;
                float v1 = acc[i][j][2*h + 1] + b1;
                if (EPI == 1) {
                    v0 = fmaxf(v0, 0.f); v1 = fmaxf(v1, 0.f);
                    __nv_bfloat162 ph;
                    ph.x = __float2bfloat16(v0); ph.y = __float2bfloat16(v1);
                    *(__nv_bfloat162*)&Cb[(size_t)head * M * N + (size_t)row * N + col] = ph;
                } else {
                    size_t o = (size_t)z * M * N + (size_t)row * N + col;
                    float2 fv; fv.x = v0; fv.y = v1;
                    *(float2*)&Cf[o] = fv;
                }
            }
        }
    }
}

// split-K reduce. EPI 0: fp32+bias -> Cf. EPI 1: bias+relu -> plain bf16 Cb.
template<int EPI>
__global__ void reduce_split(const float* __restrict__ part, const float* __restrict__ bias,
                             float* __restrict__ Cf, bf16* __restrict__ Cb,
                             int S, size_t MN, int N) {
    size_t i4 = (size_t)blockIdx.x * 256 + threadIdx.x;
    if (i4 * 4 >= MN) return;
    float4 a = {0.f, 0.f, 0.f, 0.f};
    for (int s = 0; s < S; s++) {
        float4 v = *(const float4*)(part + s * MN + i4 * 4);
        a.x += v.x; a.y += v.y; a.z += v.z; a.w += v.w;
    }
    size_t base = i4 * 4;
    int n = (int)(base % N);
    a.x += bias[n]; a.y += bias[n+1]; a.z += bias[n+2]; a.w += bias[n+3];
    if (EPI == 1) {
        a.x = fmaxf(a.x, 0.f); a.y = fmaxf(a.y, 0.f);
        a.z = fmaxf(a.z, 0.f); a.w = fmaxf(a.w, 0.f);
        __nv_bfloat162 p0, p1;
        p0.x = __float2bfloat16(a.x); p0.y = __float2bfloat16(a.y);
        p1.x = __float2bfloat16(a.z); p1.y = __float2bfloat16(a.w);
        *(__nv_bfloat162*)&Cb[base]     = p0;
        *(__nv_bfloat162*)&Cb[base + 2] = p1;
    } else {
        *(float4*)&Cf[base] = a;
    }
}

// ========================= small kernels =====================================
__global__ void l2norm_kernel(float* __restrict__ x, int rows) {
    int row = blockIdx.x * 8 + threadIdx.y;
    if (row >= rows) return;
    float* p = x + (size_t)row * De;
    int lane = threadIdx.x;
    float4 v = *(float4*)(p + lane * 4);
    float ss = v.x*v.x + v.y*v.y + v.z*v.z + v.w*v.w;
#pragma unroll
    for (int o = 16; o; o >>= 1) ss += __shfl_xor_sync(0xFFFFFFFFu, ss, o);
    float r = 1.0f / sqrtf(fmaxf(ss, 1e-12f));
    v.x *= r; v.y *= r; v.z *= r; v.w *= r;
    *(float4*)(p + lane * 4) = v;
}

// l2norm + plain bf16 copy
__global__ void l2norm_bf16(float* __restrict__ x, bf16* __restrict__ m, int rows) {
    int row = blockIdx.x * 8 + threadIdx.y;
    if (row >= rows) return;
    float* p = x + (size_t)row * De;
    int lane = threadIdx.x;
    float4 v = *(float4*)(p + lane * 4);
    float ss = v.x*v.x + v.y*v.y + v.z*v.z + v.w*v.w;
#pragma unroll
    for (int o = 16; o; o >>= 1) ss += __shfl_xor_sync(0xFFFFFFFFu, ss, o);
    float r = 1.0f / sqrtf(fmaxf(ss, 1e-12f));
    v.x *= r; v.y *= r; v.z *= r; v.w *= r;
    *(float4*)(p + lane * 4) = v;
    size_t o = (size_t)row * De + lane * 4;
    __nv_bfloat162 p0, p1;
    p0.x = __float2bfloat16(v.x); p0.y = __float2bfloat16(v.y);
    p1.x = __float2bfloat16(v.z); p1.y = __float2bfloat16(v.w);
    *(__nv_bfloat162*)&m[o]     = p0;
    *(__nv_bfloat162*)&m[o + 2] = p1;
}

__global__ void lg_kernel(const float* __restrict__ qg, const float* __restrict__ kg,
                          float* __restrict__ out) {
    int row = blockIdx.x;
    __shared__ float qs[De];
    __shared__ float red[128];
    int t = threadIdx.x;
    qs[t] = qg[(size_t)row * De + t];
    __syncthreads();
    const float* kp = kg + (size_t)t * De;
    float dot = 0.f;
#pragma unroll 8
    for (int c = 0; c < De; c++) dot = fmaf(qs[c], kp[c], dot);
    float logit = dot * INV_TAU;          // |logit| <= 5
    red[t] = __expf(logit); __syncthreads();
    for (int s = 64; s; s >>= 1) { if (t < s) red[t] += red[t + s]; __syncthreads(); }
    float lse = logf(red[0]);
    if (t == row) out[row] = lse - logit;
}

// argmax match; writes matched rows as plain bf16 (B operand)
__global__ void match_kernel(const float* __restrict__ qd, const float* __restrict__ kd,
                             bf16* __restrict__ mt, float* __restrict__ pos) {
    int row = blockIdx.x;
    int b = row / HW;
    __shared__ float qs[De];
    __shared__ float dots[64];
    __shared__ int   s_idx;
    __shared__ float s_val;
    int t = threadIdx.x;
    qs[t] = qd[(size_t)row * De + t];
    __syncthreads();
    if (t < HW) {
        const float* kp = kd + (size_t)(b * HW + t) * De;
        float d = 0.f;
#pragma unroll 8
        for (int c = 0; c < De; c++) d = fmaf(qs[c], kp[c], d);
        dots[t] = d;
    }
    __syncthreads();
    if (t == 0) {
        float bv = dots[0]; int bi = 0;
        for (int j = 1; j < HW; j++)
            if (dots[j] > bv) { bv = dots[j]; bi = j; }
        s_idx = bi; s_val = bv;
    }
    __syncthreads();
    mt[(size_t)row * De + t] = __float2bfloat16(kd[(size_t)(b * HW + s_idx) * De + t]);
    if (t == 0) pos[row] = s_val;
}

__global__ void lse_finish(const float* __restrict__ Spart, const float* __restrict__ pos,
                           float* __restrict__ out) {
    int row = blockIdx.x * 256 + threadIdx.x;
    if (row >= Nrow) return;
    float s = 0.f;
#pragma unroll
    for (int j = 0; j < NTILE; j++) s += Spart[(size_t)j * Nrow + row];
    out[row] = logf(s) - pos[row] * INV_TAU;
}

__global__ void final_kernel(const float* __restrict__ lg, const float* __restrict__ ld,
                             float* __restrict__ out) {
    int t = threadIdx.x;
    float s1 = 0.f, s2 = 0.f;
    if (t < Bn) s1 = lg[t];
    for (int j = t; j < Nrow; j += 256) s2 += ld[j];
    __shared__ float r1[256], r2[256];
    r1[t] = s1; r2[t] = s2; __syncthreads();
    for (int o = 128; o; o >>= 1) {
        if (t < o) { r1[t] += r1[t + o]; r2[t] += r2[t + o]; }
        __syncthreads();
    }
    if (t == 0) out[0] = 0.5f * (r1[0] / (float)Bn) + 0.5f * (r2[0] / (float)Nrow);
}

// ========================= host orchestration ================================
extern "C" void kernel_launch(void* const* d_in, const int* in_sizes, int n_in,
                              void* d_out, int out_size) {
    const float* feat_q = (const float*)d_in[0];
    const float* feat_k = (const float*)d_in[1];
    const float* Wg1  = (const float*)d_in[2];   const float* bg1 = (const float*)d_in[3];
    const float* Wg2  = (const float*)d_in[4];   const float* bg2 = (const float*)d_in[5];
    const float* Wd1  = (const float*)d_in[6];   const float* bd1 = (const float*)d_in[7];
    const float* Wd2  = (const float*)d_in[8];   const float* bd2 = (const float*)d_in[9];
    const float* mWg1 = (const float*)d_in[10];  const float* mbg1 = (const float*)d_in[11];
    const float* mWg2 = (const float*)d_in[12];  const float* mbg2 = (const float*)d_in[13];
    const float* mWd1 = (const float*)d_in[14];  const float* mbd1 = (const float*)d_in[15];
    const float* mWd2 = (const float*)d_in[16];  const float* mbd2 = (const float*)d_in[17];
    float* out = (float*)d_out;

    cudaFuncSetAttribute(gemm_mma<0>, cudaFuncAttributeMaxDynamicSharedMemorySize, SM_TOTAL);
    cudaFuncSetAttribute(gemm_mma<1>, cudaFuncAttributeMaxDynamicSharedMemorySize, SM_TOTAL);
    cudaFuncSetAttribute(gemm_mma<2>, cudaFuncAttributeMaxDynamicSharedMemorySize, SM_TOTAL);

#define SYM(p, s) cudaGetSymbolAddress((void**)&p, s)
    bf16 *Wd1T, *mWd1T, *Wg1T, *mWg1T, *Wg2T, *Wd2T, *mWg2T, *mWd2T;
    bf16 *Aq, *Ak, *pq, *pk, *gh, *hid, *qdm, *mt;
    float *part, *Spart, *qg, *kg, *qd, *kd, *pos, *lg, *ld;
    SYM(Wd1T, g_Wd1T); SYM(mWd1T, g_mWd1T); SYM(Wg1T, g_Wg1T); SYM(mWg1T, g_mWg1T);
    SYM(Wg2T, g_Wg2T); SYM(Wd2T, g_Wd2T); SYM(mWg2T, g_mWg2T); SYM(mWd2T, g_mWd2T);
    SYM(Aq, g_Aq); SYM(Ak, g_Ak); SYM(pq, g_pq); SYM(pk, g_pk);
    SYM(gh, g_gh); SYM(hid, g_hid); SYM(qdm, g_qdm); SYM(mt, g_mt);
    SYM(part, g_part); SYM(Spart, g_Spart);
    SYM(qg, g_qg); SYM(kg, g_kg); SYM(qd, g_qd); SYM(kd, g_kd);
    SYM(pos, g_pos); SYM(lg, g_lg); SYM(ld, g_ld);
#undef SYM

    // ---- pre-pass ----
    dim3 tb(32, 8);
    transpose_bf16<<<dim3(Dh/32, Cc/64), tb>>>(Wd1,  Wd1T,  Cc, Dh);
    transpose_bf16<<<dim3(Dh/32, Cc/64), tb>>>(mWd1, mWd1T, Cc, Dh);
    transpose_bf16<<<dim3(Dh/32, Cc/64), tb>>>(Wg1,  Wg1T,  Cc, Dh);
    transpose_bf16<<<dim3(Dh/32, Cc/64), tb>>>(mWg1, mWg1T, Cc, Dh);
    transpose_bf16<<<dim3(De/32, Dh/64), tb>>>(Wg2,  Wg2T,  Dh, De);
    transpose_bf16<<<dim3(De/32, Dh/64), tb>>>(Wd2,  Wd2T,  Dh, De);
    transpose_bf16<<<dim3(De/32, Dh/64), tb>>>(mWg2, mWg2T, Dh, De);
    transpose_bf16<<<dim3(De/32, Dh/64), tb>>>(mWd2, mWd2T, Dh, De);

    feat_prep<<<dim3(Cc/256, Bn), 256>>>(feat_q, Aq, pq);
    feat_prep<<<dim3(Cc/256, Bn), 256>>>(feat_k, Ak, pk);

    // ---- global head L1 (q+k merged, split-K 8) ----
    gemm_mma<0><<<dim3(Dh/128, 1, 16), 256, SM_TOTAL>>>(pq, pk, Wg1T, mWg1T,
        nullptr, nullptr, part, nullptr, Bn, Dh, Cc, Cc, 8, 0, 8);
    reduce_split<1><<<(Bn*Dh/4 + 255)/256, 256>>>(part, bg1, nullptr, gh, 8, (size_t)Bn*Dh, Dh);
    reduce_split<1><<<(Bn*Dh/4 + 255)/256, 256>>>(part + 8*(size_t)Bn*Dh, mbg1, nullptr,
        gh + (size_t)Bn*Dh, 8, (size_t)Bn*Dh, Dh);
    // ---- global head L2 (merged, split-K 16) ----
    gemm_mma<0><<<dim3(1, 1, 32), 256, SM_TOTAL>>>(gh, gh + (size_t)Bn*Dh, Wg2T, mWg2T,
        nullptr, nullptr, part, nullptr, Bn, De, Dh, Dh, 4, 0, 16);
    reduce_split<0><<<(Bn*De/4 + 255)/256, 256>>>(part, bg2, qg, nullptr, 16, (size_t)Bn*De, De);
    reduce_split<0><<<(Bn*De/4 + 255)/256, 256>>>(part + 16*(size_t)Bn*De, mbg2, kg, nullptr,
        16, (size_t)Bn*De, De);

    l2norm_kernel<<<(Bn + 7)/8, dim3(32, 8)>>>(qg, Bn);
    l2norm_kernel<<<(Bn + 7)/8, dim3(32, 8)>>>(kg, Bn);
    lg_kernel<<<Bn, 128>>>(qg, kg, lg);

    // ---- dense head L1 (q+k merged) ----
    gemm_mma<1><<<dim3(Dh/128, NTILE, 2), 256, SM_TOTAL>>>(Aq, Ak, Wd1T, mWd1T,
        bd1, mbd1, nullptr, hid, Nrow, Dh, Cc, Cc, 64, 0, 1);
    // ---- dense head L2 (merged, uneven split-K 3 -> 294 CTAs = 1 wave) ----
    gemm_mma<0><<<dim3(1, NTILE, 6), 256, SM_TOTAL>>>(hid, hid + (size_t)Nrow*Dh,
        Wd2T, mWd2T, nullptr, nullptr, part, nullptr, Nrow, De, Dh, Dh, 21, 1, 3);
    reduce_split<0><<<(Nrow*De/4 + 255)/256, 256>>>(part, bd2, qd, nullptr, 3, (size_t)Nrow*De, De);
    reduce_split<0><<<(Nrow*De/4 + 255)/256, 256>>>(part + 3*(size_t)Nrow*De, mbd2, kd, nullptr,
        3, (size_t)Nrow*De, De);

    l2norm_bf16<<<Nrow/8, dim3(32, 8)>>>(qd, qdm, Nrow);
    l2norm_kernel<<<Nrow/8, dim3(32, 8)>>>(kd, Nrow);

    // ---- matching + dense InfoNCE (fused exp epilogue) ----
    match_kernel<<<Nrow, 128>>>(qd, kd, mt, pos);
    gemm_mma<2><<<dim3(NTILE, NTILE, 1), 256, SM_TOTAL>>>(qdm, qdm, mt, mt,
        nullptr, nullptr, Spart, nullptr, Nrow, Nrow, De, De, 4, 0, 1);
    lse_finish<<<(Nrow + 255)/256, 256>>>(Spart, pos, ld);

    final_kernel<<<1, 256>>>(lg, ld, out);
}

// round 11
// speedup vs baseline: 5.7461x; 1.0170x over previous
#include <cuda_runtime.h>
#include <cuda_bf16.h>
#include <math.h>
#include <stdint.h>

#define Bn   128
#define HW   49
#define Cc   2048
#define Dh   2048
#define De   128
#define Nrow (Bn*HW)          // 6272
#define NTILE 49              // Nrow/128
#define INV_TAU 5.0f

typedef __nv_bfloat16 bf16;

// ========================= PTX helpers =======================================
__device__ __forceinline__ uint32_t smem_u32(const void* p) {
    uint32_t a;
    asm("{ .reg .u64 t; cvta.to.shared.u64 t, %1; cvt.u32.u64 %0, t; }" : "=r"(a) : "l"(p));
    return a;
}
__device__ __forceinline__ void cp16(uint32_t dst, const void* src) {
    asm volatile("cp.async.cg.shared.global [%0], [%1], 16;" :: "r"(dst), "l"(src));
}
#define CP_COMMIT() asm volatile("cp.async.commit_group;" ::: "memory")
#define CP_WAIT0()  asm volatile("cp.async.wait_group 0;" ::: "memory")
#define LDMX4(r0, r1, r2, r3, addr)                                            \
    asm volatile("ldmatrix.sync.aligned.m8n8.x4.shared.b16 {%0,%1,%2,%3}, [%4];" \
        : "=r"(r0), "=r"(r1), "=r"(r2), "=r"(r3) : "r"(addr))

__device__ __forceinline__ void mma16816(float* c, const uint32_t* a, const uint32_t* b) {
    asm volatile("mma.sync.aligned.m16n8k16.row.col.f32.bf16.bf16.f32 "
        "{%0,%1,%2,%3}, {%4,%5,%6,%7}, {%8,%9}, {%0,%1,%2,%3};"
        : "+f"(c[0]), "+f"(c[1]), "+f"(c[2]), "+f"(c[3])
        : "r"(a[0]), "r"(a[1]), "r"(a[2]), "r"(a[3]), "r"(b[0]), "r"(b[1]));
}

// ========================= scratch buffers ===================================
__device__ __align__(256) bf16 g_Wd1T[(size_t)Dh*Cc];
__device__ __align__(256) bf16 g_mWd1T[(size_t)Dh*Cc];
__device__ __align__(256) bf16 g_Wg1T[(size_t)Dh*Cc];
__device__ __align__(256) bf16 g_mWg1T[(size_t)Dh*Cc];
__device__ __align__(256) bf16 g_Wg2T[De*Dh], g_Wd2T[De*Dh];
__device__ __align__(256) bf16 g_mWg2T[De*Dh], g_mWd2T[De*Dh];
__device__ __align__(256) bf16 g_Aq[(size_t)Nrow*Cc], g_Ak[(size_t)Nrow*Cc];
__device__ __align__(256) bf16 g_pq[Bn*Cc], g_pk[Bn*Cc];
__device__ __align__(256) bf16 g_gh[2*(size_t)Bn*Dh];
__device__ __align__(256) bf16 g_hid[2*(size_t)Nrow*Dh];
__device__ __align__(256) bf16 g_qdm[Nrow*De];
__device__ __align__(256) bf16 g_mt[Nrow*De];
__device__ __align__(256) float g_part[6*(size_t)Nrow*De];
__device__ __align__(256) float g_partG[6*(size_t)Bn*De];
__device__ __align__(256) float g_Spart[(size_t)NTILE*Nrow];
__device__ float g_qg[Bn*De], g_kg[Bn*De];
__device__ float g_qd[Nrow*De], g_kd[Nrow*De];
__device__ float g_pos[Nrow], g_lg[Bn], g_ld[Nrow];

// ========================= pre-pass kernels ==================================
// all 8 weight transposes in one launch (all K = 2048)
struct TP { const float* W[8]; bf16* T[8]; };

__global__ void transpose_all(TP a) {
    __shared__ float t[32][65];
    int id = blockIdx.x;
    int mat, bx, by, N;
    if (id < 8192) { mat = id >> 11; int r = id & 2047; bx = r & 63; by = r >> 6; N = 2048; }
    else { int i2 = id - 8192; mat = 4 + (i2 >> 7); int r = i2 & 127; bx = r & 3; by = r >> 2; N = 128; }
    const float* W = a.W[mat];
    bf16* T = a.T[mat];
    const int K = 2048;
    int n0 = bx * 32, k0 = by * 64;
    int tx = threadIdx.x, ty = threadIdx.y;
#pragma unroll
    for (int r = 0; r < 64; r += 8)
        t[tx][r + ty] = W[(size_t)(k0 + r + ty) * N + n0 + tx];
    __syncthreads();
#pragma unroll
    for (int j = 0; j < 4; j++) {
        int nl = ty + j * 8;
        __nv_bfloat162 ph;
        ph.x = __float2bfloat16(t[nl][2 * tx]);
        ph.y = __float2bfloat16(t[nl][2 * tx + 1]);
        *(__nv_bfloat162*)&T[(size_t)(n0 + nl) * K + k0 + 2 * tx] = ph;
    }
}

// fused q+k: per-pixel bf16 convert + mean-pool bf16, float4 vectorized
__global__ void feat_prep(const float* __restrict__ fq, const float* __restrict__ fk,
                          bf16* __restrict__ Aqo, bf16* __restrict__ Ako,
                          bf16* __restrict__ pqo, bf16* __restrict__ pko) {
    const float* f = blockIdx.z ? fk : fq;
    bf16* A   = blockIdx.z ? Ako : Aqo;
    bf16* pool = blockIdx.z ? pko : pqo;
    int b = blockIdx.y;
    int c4 = blockIdx.x * 256 + threadIdx.x;       // 0..511 (Cc/4)
    const float4* p = (const float4*)(f + (size_t)b * HW * Cc) + c4;
    float4 s = {0.f, 0.f, 0.f, 0.f};
#pragma unroll
    for (int i = 0; i < HW; i++) {
        float4 v = p[(size_t)i * (Cc / 4)];
        s.x += v.x; s.y += v.y; s.z += v.z; s.w += v.w;
        __nv_bfloat162 p0, p1;
        p0.x = __float2bfloat16(v.x); p0.y = __float2bfloat16(v.y);
        p1.x = __float2bfloat16(v.z); p1.y = __float2bfloat16(v.w);
        size_t o = ((size_t)b * HW + i) * Cc + c4 * 4;
        *(__nv_bfloat162*)&A[o]     = p0;
        *(__nv_bfloat162*)&A[o + 2] = p1;
    }
    const float inv = 1.0f / 49.0f;
    __nv_bfloat162 q0, q1;
    q0.x = __float2bfloat16(s.x * inv); q0.y = __float2bfloat16(s.y * inv);
    q1.x = __float2bfloat16(s.z * inv); q1.y = __float2bfloat16(s.w * inv);
    size_t o = (size_t)b * Cc + c4 * 4;
    *(__nv_bfloat162*)&pool[o]     = q0;
    *(__nv_bfloat162*)&pool[o + 2] = q1;
}

// ========================= op-table mma.sync GEMM ============================
// Table entry selected by (is_global_tile ? 2 : 0) + head.
// EPI 0: fp32 partial at op.Cf + kidx*op.M*N
// EPI 1: bias+relu -> plain bf16 at op.Cb
// EPI 2: exp-rowsum -> op.Cf[blockIdx.x*op.M + row]
struct GOp { const bf16* A; const bf16* B; const float* bias; float* Cf; bf16* Cb; int M; };
struct GOps { GOp op[4]; };

#define ROWB 80
#define MATB (128*ROWB)         // 10240
#define STGB (2*MATB)           // 20480
#define SM_TOTAL (2*STGB)       // 40960

template<int EPI>
__global__ __launch_bounds__(256, 2)
void gemm_mma(GOps ops, int N, int ldA, int ldB, int nbC, int remC, int nzk, int yglob) {
    extern __shared__ char smem[];
    const uint32_t sb = smem_u32(smem);
    const int tid = threadIdx.x;
    const int wid = tid >> 5;
    const int lid = tid & 31;
    const int wm = wid >> 2;
    const int wn = wid & 3;
    const int g = lid >> 2;
    const int t = lid & 3;
    const int z = blockIdx.z;
    const int head = z / nzk;
    const int kidx = z - head * nzk;
    const bool isg = ((int)blockIdx.y == yglob);
    const GOp op = ops.op[(isg ? 2 : 0) + head];
    const int bm = isg ? 0 : blockIdx.y * 128;
    const int bn = blockIdx.x * 128;
    const int kbeg = (kidx * nbC + min(kidx, remC)) * 32;
    const int nch = nbC + (kidx < remC ? 1 : 0);

    const bf16* A = op.A + (size_t)bm * ldA + kbeg;
    const bf16* B = op.B + (size_t)bn * ldB + kbeg;

    const int r0 = tid >> 2, c0 = tid & 3;

    float acc[4][4][4];
#pragma unroll
    for (int i = 0; i < 4; i++)
#pragma unroll
        for (int j = 0; j < 4; j++)
#pragma unroll
            for (int c = 0; c < 4; c++) acc[i][j][c] = 0.f;

#pragma unroll
    for (int s = 0; s < 2; s++) {
        int r = r0 + s * 64;
        cp16(sb + 0*MATB + r*ROWB + c0*16, A + (size_t)r * ldA + c0 * 8);
        cp16(sb + 1*MATB + r*ROWB + c0*16, B + (size_t)r * ldB + c0 * 8);
    }
    CP_COMMIT();

    const uint32_t a_lm = (uint32_t)((wm*64 + (lid & 7) + ((lid >> 3) & 1) * 8) * ROWB
                                     + ((lid >> 4) & 1) * 16);
    const uint32_t b_lm = (uint32_t)((wn*32 + (lid & 7) + ((lid >> 4) & 1) * 8) * ROWB
                                     + ((lid >> 3) & 1) * 16);

    for (int ch = 0; ch < nch; ch++) {
        CP_WAIT0();
        __syncthreads();
        if (ch + 1 < nch) {
            const int k0 = (ch + 1) * 32;
            uint32_t st = sb + ((ch + 1) & 1) * STGB;
#pragma unroll
            for (int s = 0; s < 2; s++) {
                int r = r0 + s * 64;
                cp16(st + 0*MATB + r*ROWB + c0*16, A + (size_t)r * ldA + k0 + c0 * 8);
                cp16(st + 1*MATB + r*ROWB + c0*16, B + (size_t)r * ldB + k0 + c0 * 8);
            }
            CP_COMMIT();
        }
        const uint32_t st = sb + (ch & 1) * STGB;
#pragma unroll
        for (int ks = 0; ks < 2; ks++) {
            uint32_t ah[4][4];
#pragma unroll
            for (int i = 0; i < 4; i++) {
                uint32_t aa = st + a_lm + i * (16 * ROWB) + ks * 32;
                LDMX4(ah[i][0], ah[i][1], ah[i][2], ah[i][3], aa);
            }
#pragma unroll
            for (int jp = 0; jp < 2; jp++) {
                uint32_t bh[2][2];
                uint32_t bb = st + 1*MATB + b_lm + jp * (16 * ROWB) + ks * 32;
                LDMX4(bh[0][0], bh[0][1], bh[1][0], bh[1][1], bb);
#pragma unroll
                for (int i = 0; i < 4; i++)
#pragma unroll
                    for (int jj = 0; jj < 2; jj++)
                        mma16816(acc[i][jp*2 + jj], ah[i], bh[jj]);
            }
        }
        __syncthreads();
    }

    // ---- epilogue ----
    if (EPI == 2) {
        float rs[8];
#pragma unroll
        for (int i = 0; i < 4; i++)
#pragma unroll
            for (int h = 0; h < 2; h++) {
                float s = 0.f;
#pragma unroll
                for (int j = 0; j < 4; j++)
                    s += __expf(acc[i][j][2*h] * INV_TAU)
                       + __expf(acc[i][j][2*h + 1] * INV_TAU);
                s += __shfl_xor_sync(0xFFFFFFFFu, s, 1);
                s += __shfl_xor_sync(0xFFFFFFFFu, s, 2);
                rs[i*2 + h] = s;
            }
        float* sm = (float*)smem;
        __syncthreads();
        if (t == 0) {
#pragma unroll
            for (int idx = 0; idx < 8; idx++) {
                int i = idx >> 1, h = idx & 1;
                int row = wm*64 + i*16 + g + h*8;
                sm[row*4 + wn] = rs[idx];
            }
        }
        __syncthreads();
        if (tid < 128) {
            float tot = sm[tid*4+0] + sm[tid*4+1] + sm[tid*4+2] + sm[tid*4+3];
            op.Cf[(size_t)blockIdx.x * op.M + bm + tid] = tot;
        }
        return;
    }
#pragma unroll
    for (int i = 0; i < 4; i++) {
        int row0 = bm + wm*64 + i*16 + g;
#pragma unroll
        for (int j = 0; j < 4; j++) {
            int col = bn + wn*32 + j*8 + 2*t;
            float b0 = 0.f, b1 = 0.f;
            if (EPI == 1) { b0 = op.bias[col]; b1 = op.bias[col + 1]; }
#pragma unroll
            for (int h = 0; h < 2; h++) {
                int row = row0 + h*8;
                float v0 = acc[i][j][2*h]     + b0;
                float v1 = acc[i][j][2*h + 1] + b1;
                if (EPI == 1) {
                    v0 = fmaxf(v0, 0.f); v1 = fmaxf(v1, 0.f);
                    __nv_bfloat162 ph;
                    ph.x = __float2bfloat16(v0); ph.y = __float2bfloat16(v1);
                    *(__nv_bfloat162*)&op.Cb[(size_t)row * N + col] = ph;
                } else {
                    size_t o = (size_t)kidx * op.M * N + (size_t)row * N + col;
                    float2 fv; fv.x = v0; fv.y = v1;
                    *(float2*)&op.Cf[o] = fv;
                }
            }
        }
    }
}

// ========================= merged split-K reduce (4 segments) ================
struct ROp { const float* part; const float* bias; float* Cf; int M; };
struct ROps { ROp op[4]; };

__global__ void reduce4(ROps r) {
    int id = blockIdx.x;
    int seg, local;
    if (id < 784)       { seg = 0; local = id; }
    else if (id < 1568) { seg = 1; local = id - 784; }
    else if (id < 1584) { seg = 2; local = id - 1568; }
    else                { seg = 3; local = id - 1584; }
    ROp op = r.op[seg];
    size_t MN = (size_t)op.M * De;
    size_t i4 = (size_t)local * 256 + threadIdx.x;
    if (i4 * 4 >= MN) return;
    float4 a = {0.f, 0.f, 0.f, 0.f};
#pragma unroll
    for (int s = 0; s < 3; s++) {
        float4 v = *(const float4*)(op.part + s * MN + i4 * 4);
        a.x += v.x; a.y += v.y; a.z += v.z; a.w += v.w;
    }
    size_t base = i4 * 4;
    int n = (int)(base & (De - 1));
    a.x += op.bias[n]; a.y += op.bias[n+1]; a.z += op.bias[n+2]; a.w += op.bias[n+3];
    *(float4*)&op.Cf[base] = a;
}

// ========================= merged l2norm (qg, kg, qd->qdm, kd) ===============
__global__ void l2norm_all(float* __restrict__ qg, float* __restrict__ kg,
                           float* __restrict__ qd, float* __restrict__ kd,
                           bf16* __restrict__ qdm) {
    int r = blockIdx.x * 8 + threadIdx.y;
    float* x;
    bf16* mo = nullptr;
    if (r < Bn) x = qg + (size_t)r * De;
    else if (r < 2*Bn) x = kg + (size_t)(r - Bn) * De;
    else if (r < 2*Bn + Nrow) {
        int rr = r - 2*Bn;
        x = qd + (size_t)rr * De;
        mo = qdm + (size_t)rr * De;
    } else {
        x = kd + (size_t)(r - 2*Bn - Nrow) * De;
    }
    int lane = threadIdx.x;
    float4 v = *(float4*)(x + lane * 4);
    float ss = v.x*v.x + v.y*v.y + v.z*v.z + v.w*v.w;
#pragma unroll
    for (int o = 16; o; o >>= 1) ss += __shfl_xor_sync(0xFFFFFFFFu, ss, o);
    float rr = 1.0f / sqrtf(fmaxf(ss, 1e-12f));
    v.x *= rr; v.y *= rr; v.z *= rr; v.w *= rr;
    *(float4*)(x + lane * 4) = v;
    if (mo) {
        __nv_bfloat162 p0, p1;
        p0.x = __float2bfloat16(v.x); p0.y = __float2bfloat16(v.y);
        p1.x = __float2bfloat16(v.z); p1.y = __float2bfloat16(v.w);
        *(__nv_bfloat162*)&mo[lane * 4]     = p0;
        *(__nv_bfloat162*)&mo[lane * 4 + 2] = p1;
    }
}

// ========================= merged lg + match =================================
__global__ void lg_match(const float* __restrict__ qg, const float* __restrict__ kg,
                         float* __restrict__ lgout,
                         const float* __restrict__ qd, const float* __restrict__ kd,
                         bf16* __restrict__ mt, float* __restrict__ pos) {
    __shared__ float qs[128];
    __shared__ float buf[128];
    __shared__ int s_idx;
    int t = threadIdx.x;
    if (blockIdx.x < Bn) {
        int row = blockIdx.x;
        qs[t] = qg[(size_t)row * De + t];
        __syncthreads();
        const float* kp = kg + (size_t)t * De;
        float dot = 0.f;
#pragma unroll 8
        for (int c = 0; c < De; c++) dot = fmaf(qs[c], kp[c], dot);
        float logit = dot * INV_TAU;
        buf[t] = __expf(logit); __syncthreads();
        for (int s = 64; s; s >>= 1) { if (t < s) buf[t] += buf[t + s]; __syncthreads(); }
        if (t == row) lgout[row] = logf(buf[0]) - logit;
    } else {
        int row = blockIdx.x - Bn;
        int b = row / HW;
        qs[t] = qd[(size_t)row * De + t];
        __syncthreads();
        if (t < HW) {
            const float* kp = kd + (size_t)(b * HW + t) * De;
            float d = 0.f;
#pragma unroll 8
            for (int c = 0; c < De; c++) d = fmaf(qs[c], kp[c], d);
            buf[t] = d;
        }
        __syncthreads();
        if (t == 0) {
            float bv = buf[0]; int bi = 0;
            for (int j = 1; j < HW; j++)
                if (buf[j] > bv) { bv = buf[j]; bi = j; }
            s_idx = bi; pos[row] = bv;
        }
        __syncthreads();
        mt[(size_t)row * De + t] = __float2bfloat16(kd[(size_t)(b * HW + s_idx) * De + t]);
    }
}

__global__ void lse_finish(const float* __restrict__ Spart, const float* __restrict__ pos,
                           float* __restrict__ out) {
    int row = blockIdx.x * 256 + threadIdx.x;
    if (row >= Nrow) return;
    float s = 0.f;
#pragma unroll
    for (int j = 0; j < NTILE; j++) s += Spart[(size_t)j * Nrow + row];
    out[row] = logf(s) - pos[row] * INV_TAU;
}

__global__ void final_kernel(const float* __restrict__ lg, const float* __restrict__ ld,
                             float* __restrict__ out) {
    int t = threadIdx.x;
    float s1 = 0.f, s2 = 0.f;
    if (t < Bn) s1 = lg[t];
    for (int j = t; j < Nrow; j += 256) s2 += ld[j];
    __shared__ float r1[256], r2[256];
    r1[t] = s1; r2[t] = s2; __syncthreads();
    for (int o = 128; o; o >>= 1) {
        if (t < o) { r1[t] += r1[t + o]; r2[t] += r2[t + o]; }
        __syncthreads();
    }
    if (t == 0) out[0] = 0.5f * (r1[0] / (float)Bn) + 0.5f * (r2[0] / (float)Nrow);
}

// ========================= host orchestration ================================
extern "C" void kernel_launch(void* const* d_in, const int* in_sizes, int n_in,
                              void* d_out, int out_size) {
    const float* feat_q = (const float*)d_in[0];
    const float* feat_k = (const float*)d_in[1];
    const float* Wg1  = (const float*)d_in[2];   const float* bg1 = (const float*)d_in[3];
    const float* Wg2  = (const float*)d_in[4];   const float* bg2 = (const float*)d_in[5];
    const float* Wd1  = (const float*)d_in[6];   const float* bd1 = (const float*)d_in[7];
    const float* Wd2  = (const float*)d_in[8];   const float* bd2 = (const float*)d_in[9];
    const float* mWg1 = (const float*)d_in[10];  const float* mbg1 = (const float*)d_in[11];
    const float* mWg2 = (const float*)d_in[12];  const float* mbg2 = (const float*)d_in[13];
    const float* mWd1 = (const float*)d_in[14];  const float* mbd1 = (const float*)d_in[15];
    const float* mWd2 = (const float*)d_in[16];  const float* mbd2 = (const float*)d_in[17];
    float* out = (float*)d_out;

    cudaFuncSetAttribute(gemm_mma<0>, cudaFuncAttributeMaxDynamicSharedMemorySize, SM_TOTAL);
    cudaFuncSetAttribute(gemm_mma<1>, cudaFuncAttributeMaxDynamicSharedMemorySize, SM_TOTAL);
    cudaFuncSetAttribute(gemm_mma<2>, cudaFuncAttributeMaxDynamicSharedMemorySize, SM_TOTAL);

#define SYM(p, s) cudaGetSymbolAddress((void**)&p, s)
    bf16 *Wd1T, *mWd1T, *Wg1T, *mWg1T, *Wg2T, *Wd2T, *mWg2T, *mWd2T;
    bf16 *Aq, *Ak, *pq, *pk, *gh, *hid, *qdm, *mt;
    float *part, *partG, *Spart, *qg, *kg, *qd, *kd, *pos, *lg, *ld;
    SYM(Wd1T, g_Wd1T); SYM(mWd1T, g_mWd1T); SYM(Wg1T, g_Wg1T); SYM(mWg1T, g_mWg1T);
    SYM(Wg2T, g_Wg2T); SYM(Wd2T, g_Wd2T); SYM(mWg2T, g_mWg2T); SYM(mWd2T, g_mWd2T);
    SYM(Aq, g_Aq); SYM(Ak, g_Ak); SYM(pq, g_pq); SYM(pk, g_pk);
    SYM(gh, g_gh); SYM(hid, g_hid); SYM(qdm, g_qdm); SYM(mt, g_mt);
    SYM(part, g_part); SYM(partG, g_partG); SYM(Spart, g_Spart);
    SYM(qg, g_qg); SYM(kg, g_kg); SYM(qd, g_qd); SYM(kd, g_kd);
    SYM(pos, g_pos); SYM(lg, g_lg); SYM(ld, g_ld);
#undef SYM

    // ---- 1. all weight transposes ----
    TP tp;
    tp.W[0] = Wd1;  tp.T[0] = Wd1T;
    tp.W[1] = mWd1; tp.T[1] = mWd1T;
    tp.W[2] = Wg1;  tp.T[2] = Wg1T;
    tp.W[3] = mWg1; tp.T[3] = mWg1T;
    tp.W[4] = Wg2;  tp.T[4] = Wg2T;
    tp.W[5] = Wd2;  tp.T[5] = Wd2T;
    tp.W[6] = mWg2; tp.T[6] = mWg2T;
    tp.W[7] = mWd2; tp.T[7] = mWd2T;
    transpose_all<<<8704, dim3(32, 8)>>>(tp);

    // ---- 2. activations ----
    feat_prep<<<dim3(2, Bn, 2), 256>>>(feat_q, feat_k, Aq, Ak, pq, pk);

    // ---- 3. L1 merged: dense (y<49) + global (y==49), full-K, bias+relu bf16 ----
    {
        GOps o;
        o.op[0] = { Aq, Wd1T,  bd1,  nullptr, hid,                       Nrow };
        o.op[1] = { Ak, mWd1T, mbd1, nullptr, hid + (size_t)Nrow*Dh,     Nrow };
        o.op[2] = { pq, Wg1T,  bg1,  nullptr, gh,                        Bn };
        o.op[3] = { pk, mWg1T, mbg1, nullptr, gh + (size_t)Bn*Dh,        Bn };
        gemm_mma<1><<<dim3(Dh/128, NTILE + 1, 2), 256, SM_TOTAL>>>(
            o, Dh, Cc, Cc, 64, 0, 1, NTILE);
    }

    // ---- 4. L2 merged: down-proj (y<49) + global L2 (y==49), split-K 3 ----
    {
        GOps o;
        o.op[0] = { hid,                   Wd2T,  nullptr, part,                       nullptr, Nrow };
        o.op[1] = { hid + (size_t)Nrow*Dh, mWd2T, nullptr, part + 3*(size_t)Nrow*De,   nullptr, Nrow };
        o.op[2] = { gh,                    Wg2T,  nullptr, partG,                      nullptr, Bn };
        o.op[3] = { gh + (size_t)Bn*Dh,    mWg2T, nullptr, partG + 3*(size_t)Bn*De,    nullptr, Bn };
        gemm_mma<0><<<dim3(1, NTILE + 1, 6), 256, SM_TOTAL>>>(
            o, De, Dh, Dh, 21, 1, 3, NTILE);
    }

    // ---- 5. merged reduce (qd, kd, qg, kg) ----
    {
        ROps r;
        r.op[0] = { part,                     bd2,  qd, Nrow };
        r.op[1] = { part + 3*(size_t)Nrow*De, mbd2, kd, Nrow };
        r.op[2] = { partG,                    bg2,  qg, Bn };
        r.op[3] = { partG + 3*(size_t)Bn*De,  mbg2, kg, Bn };
        reduce4<<<1600, 256>>>(r);
    }

    // ---- 6. merged l2norm ----
    l2norm_all<<<(2*Bn + 2*Nrow)/8, dim3(32, 8)>>>(qg, kg, qd, kd, qdm);

    // ---- 7. merged lg + match ----
    lg_match<<<Bn + Nrow, 128>>>(qg, kg, lg, qd, kd, mt, pos);

    // ---- 8. S-GEMM with fused exp epilogue ----
    {
        GOps o;
        o.op[0] = { qdm, mt, nullptr, Spart, nullptr, Nrow };
        o.op[1] = o.op[0]; o.op[2] = o.op[0]; o.op[3] = o.op[0];
        gemm_mma<2><<<dim3(NTILE, NTILE, 1), 256, SM_TOTAL>>>(
            o, Nrow, De, De, 4, 0, 1, -1);
    }

    // ---- 9/10. finish ----
    lse_finish<<<(Nrow + 255)/256, 256>>>(Spart, pos, ld);
    final_kernel<<<1, 256>>>(lg, ld, out);
}

// round 12
// speedup vs baseline: 6.1937x; 1.0779x over previous
#include <cuda_runtime.h>
#include <cuda_bf16.h>
#include <math.h>
#include <stdint.h>

#define Bn   128
#define HW   49
#define Cc   2048
#define Dh   2048
#define De   128
#define Nrow (Bn*HW)          // 6272
#define NTILE 49              // Nrow/128
#define INV_TAU 5.0f

typedef __nv_bfloat16 bf16;

// ========================= PTX helpers =======================================
__device__ __forceinline__ uint32_t smem_u32(const void* p) {
    uint32_t a;
    asm("{ .reg .u64 t; cvta.to.shared.u64 t, %1; cvt.u32.u64 %0, t; }" : "=r"(a) : "l"(p));
    return a;
}
__device__ __forceinline__ void cp16(uint32_t dst, const void* src) {
    asm volatile("cp.async.cg.shared.global [%0], [%1], 16;" :: "r"(dst), "l"(src));
}
#define CP_COMMIT() asm volatile("cp.async.commit_group;" ::: "memory")
#define CP_WAIT0()  asm volatile("cp.async.wait_group 0;" ::: "memory")
#define LDMX4(r0, r1, r2, r3, addr)                                            \
    asm volatile("ldmatrix.sync.aligned.m8n8.x4.shared.b16 {%0,%1,%2,%3}, [%4];" \
        : "=r"(r0), "=r"(r1), "=r"(r2), "=r"(r3) : "r"(addr))

__device__ __forceinline__ void mma16816(float* c, const uint32_t* a, const uint32_t* b) {
    asm volatile("mma.sync.aligned.m16n8k16.row.col.f32.bf16.bf16.f32 "
        "{%0,%1,%2,%3}, {%4,%5,%6,%7}, {%8,%9}, {%0,%1,%2,%3};"
        : "+f"(c[0]), "+f"(c[1]), "+f"(c[2]), "+f"(c[3])
        : "r"(a[0]), "r"(a[1]), "r"(a[2]), "r"(a[3]), "r"(b[0]), "r"(b[1]));
}

// ========================= scratch buffers ===================================
__device__ __align__(256) bf16 g_Wd1T[(size_t)Dh*Cc];
__device__ __align__(256) bf16 g_mWd1T[(size_t)Dh*Cc];
__device__ __align__(256) bf16 g_Wg1T[(size_t)Dh*Cc];
__device__ __align__(256) bf16 g_mWg1T[(size_t)Dh*Cc];
__device__ __align__(256) bf16 g_Wg2T[De*Dh], g_Wd2T[De*Dh];
__device__ __align__(256) bf16 g_mWg2T[De*Dh], g_mWd2T[De*Dh];
__device__ __align__(256) bf16 g_Aq[(size_t)Nrow*Cc], g_Ak[(size_t)Nrow*Cc];
__device__ __align__(256) bf16 g_pq[Bn*Cc], g_pk[Bn*Cc];
__device__ __align__(256) bf16 g_gh[2*(size_t)Bn*Dh];
__device__ __align__(256) bf16 g_hid[2*(size_t)Nrow*Dh];
__device__ __align__(256) bf16 g_qdm[Nrow*De];
__device__ __align__(256) bf16 g_mt[Nrow*De];
__device__ __align__(256) float g_Spart[(size_t)NTILE*Nrow];
__device__ float g_qg[Bn*De], g_kg[Bn*De];
__device__ float g_qd[Nrow*De], g_kd[Nrow*De];
__device__ float g_pos[Nrow], g_lg[Bn], g_ld[Nrow];

// ========================= pre-pass kernels ==================================
struct TP { const float* W[8]; bf16* T[8]; };

__global__ void transpose_all(TP a) {
    __shared__ float t[32][65];
    int id = blockIdx.x;
    int mat, bx, by, N;
    if (id < 8192) { mat = id >> 11; int r = id & 2047; bx = r & 63; by = r >> 6; N = 2048; }
    else { int i2 = id - 8192; mat = 4 + (i2 >> 7); int r = i2 & 127; bx = r & 3; by = r >> 2; N = 128; }
    const float* W = a.W[mat];
    bf16* T = a.T[mat];
    const int K = 2048;
    int n0 = bx * 32, k0 = by * 64;
    int tx = threadIdx.x, ty = threadIdx.y;
#pragma unroll
    for (int r = 0; r < 64; r += 8)
        t[tx][r + ty] = W[(size_t)(k0 + r + ty) * N + n0 + tx];
    __syncthreads();
#pragma unroll
    for (int j = 0; j < 4; j++) {
        int nl = ty + j * 8;
        __nv_bfloat162 ph;
        ph.x = __float2bfloat16(t[nl][2 * tx]);
        ph.y = __float2bfloat16(t[nl][2 * tx + 1]);
        *(__nv_bfloat162*)&T[(size_t)(n0 + nl) * K + k0 + 2 * tx] = ph;
    }
}

// fused q+k: per-pixel bf16 convert + mean-pool; HW split across two half-warpsets
__global__ void feat_prep(const float* __restrict__ fq, const float* __restrict__ fk,
                          bf16* __restrict__ Aqo, bf16* __restrict__ Ako,
                          bf16* __restrict__ pqo, bf16* __restrict__ pko) {
    __shared__ float4 ps[128];
    const float* f = blockIdx.z ? fk : fq;
    bf16* A    = blockIdx.z ? Ako : Aqo;
    bf16* pool = blockIdx.z ? pko : pqo;
    int b = blockIdx.y;
    int half = threadIdx.x >> 7;                   // 0 or 1
    int cl = threadIdx.x & 127;
    int c4 = blockIdx.x * 128 + cl;                // 0..511
    const float4* p = (const float4*)(f + (size_t)b * HW * Cc) + c4;
    int i0 = half ? 25 : 0, i1 = half ? 49 : 25;
    float4 s = {0.f, 0.f, 0.f, 0.f};
    for (int i = i0; i < i1; i++) {
        float4 v = p[(size_t)i * (Cc / 4)];
        s.x += v.x; s.y += v.y; s.z += v.z; s.w += v.w;
        __nv_bfloat162 p0, p1;
        p0.x = __float2bfloat16(v.x); p0.y = __float2bfloat16(v.y);
        p1.x = __float2bfloat16(v.z); p1.y = __float2bfloat16(v.w);
        size_t o = ((size_t)b * HW + i) * Cc + c4 * 4;
        *(__nv_bfloat162*)&A[o]     = p0;
        *(__nv_bfloat162*)&A[o + 2] = p1;
    }
    if (half) ps[cl] = s;
    __syncthreads();
    if (!half) {
        float4 s2 = ps[cl];
        s.x += s2.x; s.y += s2.y; s.z += s2.z; s.w += s2.w;
        const float inv = 1.0f / 49.0f;
        __nv_bfloat162 q0, q1;
        q0.x = __float2bfloat16(s.x * inv); q0.y = __float2bfloat16(s.y * inv);
        q1.x = __float2bfloat16(s.z * inv); q1.y = __float2bfloat16(s.w * inv);
        size_t o = (size_t)b * Cc + c4 * 4;
        *(__nv_bfloat162*)&pool[o]     = q0;
        *(__nv_bfloat162*)&pool[o + 2] = q1;
    }
}

// ========================= op-table mma.sync GEMM (BK=64) ====================
// EPI 1: bias+relu -> plain bf16 at op.Cb
// EPI 2: exp-rowsum -> op.Cf[blockIdx.x*op.M + row]
// EPI 3: bias -> fp32 at op.Cf
struct GOp { const bf16* A; const bf16* B; const float* bias; float* Cf; bf16* Cb; int M; };
struct GOps { GOp op[4]; };

#define ROWB 144
#define MATB (128*ROWB)         // 18432
#define STGB (2*MATB)           // 36864
#define SM_TOTAL (2*STGB)       // 73728

template<int EPI>
__global__ __launch_bounds__(256, 2)
void gemm_mma(GOps ops, int N, int ldA, int ldB, int nbC, int remC, int nzk, int yglob) {
    extern __shared__ char smem[];
    const uint32_t sb = smem_u32(smem);
    const int tid = threadIdx.x;
    const int wid = tid >> 5;
    const int lid = tid & 31;
    const int wm = wid >> 2;
    const int wn = wid & 3;
    const int g = lid >> 2;
    const int t = lid & 3;
    const int z = blockIdx.z;
    const int head = z / nzk;
    const int kidx = z - head * nzk;
    const bool isg = ((int)blockIdx.y == yglob);
    const GOp op = ops.op[(isg ? 2 : 0) + head];
    const int bm = isg ? 0 : blockIdx.y * 128;
    const int bn = blockIdx.x * 128;
    const int kbeg = (kidx * nbC + min(kidx, remC)) * 64;
    const int nch = nbC + (kidx < remC ? 1 : 0);

    const bf16* A = op.A + (size_t)bm * ldA + kbeg;
    const bf16* B = op.B + (size_t)bn * ldB + kbeg;

    const int r0 = tid >> 3, c0 = tid & 7;

    float acc[4][4][4];
#pragma unroll
    for (int i = 0; i < 4; i++)
#pragma unroll
        for (int j = 0; j < 4; j++)
#pragma unroll
            for (int c = 0; c < 4; c++) acc[i][j][c] = 0.f;

    // prologue: chunk 0 -> stage 0
#pragma unroll
    for (int s = 0; s < 4; s++) {
        int r = r0 + s * 32;
        cp16(sb + 0*MATB + r*ROWB + c0*16, A + (size_t)r * ldA + c0 * 8);
        cp16(sb + 1*MATB + r*ROWB + c0*16, B + (size_t)r * ldB + c0 * 8);
    }
    CP_COMMIT();

    const uint32_t a_lm = (uint32_t)((wm*64 + (lid & 7) + ((lid >> 3) & 1) * 8) * ROWB
                                     + ((lid >> 4) & 1) * 16);
    const uint32_t b_lm = (uint32_t)((wn*32 + (lid & 7) + ((lid >> 4) & 1) * 8) * ROWB
                                     + ((lid >> 3) & 1) * 16);

    for (int ch = 0; ch < nch; ch++) {
        CP_WAIT0();
        __syncthreads();
        if (ch + 1 < nch) {
            const int k0 = (ch + 1) * 64;
            uint32_t st = sb + ((ch + 1) & 1) * STGB;
#pragma unroll
            for (int s = 0; s < 4; s++) {
                int r = r0 + s * 32;
                cp16(st + 0*MATB + r*ROWB + c0*16, A + (size_t)r * ldA + k0 + c0 * 8);
                cp16(st + 1*MATB + r*ROWB + c0*16, B + (size_t)r * ldB + k0 + c0 * 8);
            }
            CP_COMMIT();
        }
        const uint32_t st = sb + (ch & 1) * STGB;
#pragma unroll
        for (int ks = 0; ks < 4; ks++) {
            const uint32_t koff = ks * 32;
            uint32_t ah[4][4];
#pragma unroll
            for (int i = 0; i < 4; i++) {
                uint32_t aa = st + a_lm + i * (16 * ROWB) + koff;
                LDMX4(ah[i][0], ah[i][1], ah[i][2], ah[i][3], aa);
            }
#pragma unroll
            for (int jp = 0; jp < 2; jp++) {
                uint32_t bh[2][2];
                uint32_t bb = st + 1*MATB + b_lm + jp * (16 * ROWB) + koff;
                LDMX4(bh[0][0], bh[0][1], bh[1][0], bh[1][1], bb);
#pragma unroll
                for (int i = 0; i < 4; i++)
#pragma unroll
                    for (int jj = 0; jj < 2; jj++)
                        mma16816(acc[i][jp*2 + jj], ah[i], bh[jj]);
            }
        }
        __syncthreads();
    }

    // ---- epilogue ----
    if (EPI == 2) {
        float rs[8];
#pragma unroll
        for (int i = 0; i < 4; i++)
#pragma unroll
            for (int h = 0; h < 2; h++) {
                float s = 0.f;
#pragma unroll
                for (int j = 0; j < 4; j++)
                    s += __expf(acc[i][j][2*h] * INV_TAU)
                       + __expf(acc[i][j][2*h + 1] * INV_TAU);
                s += __shfl_xor_sync(0xFFFFFFFFu, s, 1);
                s += __shfl_xor_sync(0xFFFFFFFFu, s, 2);
                rs[i*2 + h] = s;
            }
        float* sm = (float*)smem;
        __syncthreads();
        if (t == 0) {
#pragma unroll
            for (int idx = 0; idx < 8; idx++) {
                int i = idx >> 1, h = idx & 1;
                int row = wm*64 + i*16 + g + h*8;
                sm[row*4 + wn] = rs[idx];
            }
        }
        __syncthreads();
        if (tid < 128) {
            float tot = sm[tid*4+0] + sm[tid*4+1] + sm[tid*4+2] + sm[tid*4+3];
            op.Cf[(size_t)blockIdx.x * op.M + bm + tid] = tot;
        }
        return;
    }
#pragma unroll
    for (int i = 0; i < 4; i++) {
        int row0 = bm + wm*64 + i*16 + g;
#pragma unroll
        for (int j = 0; j < 4; j++) {
            int col = bn + wn*32 + j*8 + 2*t;
            float b0 = op.bias[col], b1 = op.bias[col + 1];
#pragma unroll
            for (int h = 0; h < 2; h++) {
                int row = row0 + h*8;
                float v0 = acc[i][j][2*h]     + b0;
                float v1 = acc[i][j][2*h + 1] + b1;
                if (EPI == 1) {
                    v0 = fmaxf(v0, 0.f); v1 = fmaxf(v1, 0.f);
                    __nv_bfloat162 ph;
                    ph.x = __float2bfloat16(v0); ph.y = __float2bfloat16(v1);
                    *(__nv_bfloat162*)&op.Cb[(size_t)row * N + col] = ph;
                } else {              // EPI 3: bias, fp32, direct
                    float2 fv; fv.x = v0; fv.y = v1;
                    *(float2*)&op.Cf[(size_t)row * N + col] = fv;
                }
            }
        }
    }
}

// ========================= merged l2norm (qg, kg, qd->qdm, kd) ===============
__global__ void l2norm_all(float* __restrict__ qg, float* __restrict__ kg,
                           float* __restrict__ qd, float* __restrict__ kd,
                           bf16* __restrict__ qdm) {
    int r = blockIdx.x * 8 + threadIdx.y;
    float* x;
    bf16* mo = nullptr;
    if (r < Bn) x = qg + (size_t)r * De;
    else if (r < 2*Bn) x = kg + (size_t)(r - Bn) * De;
    else if (r < 2*Bn + Nrow) {
        int rr = r - 2*Bn;
        x = qd + (size_t)rr * De;
        mo = qdm + (size_t)rr * De;
    } else {
        x = kd + (size_t)(r - 2*Bn - Nrow) * De;
    }
    int lane = threadIdx.x;
    float4 v = *(float4*)(x + lane * 4);
    float ss = v.x*v.x + v.y*v.y + v.z*v.z + v.w*v.w;
#pragma unroll
    for (int o = 16; o; o >>= 1) ss += __shfl_xor_sync(0xFFFFFFFFu, ss, o);
    float rr = 1.0f / sqrtf(fmaxf(ss, 1e-12f));
    v.x *= rr; v.y *= rr; v.z *= rr; v.w *= rr;
    *(float4*)(x + lane * 4) = v;
    if (mo) {
        __nv_bfloat162 p0, p1;
        p0.x = __float2bfloat16(v.x); p0.y = __float2bfloat16(v.y);
        p1.x = __float2bfloat16(v.z); p1.y = __float2bfloat16(v.w);
        *(__nv_bfloat162*)&mo[lane * 4]     = p0;
        *(__nv_bfloat162*)&mo[lane * 4 + 2] = p1;
    }
}

// ========================= merged lg + match =================================
__global__ void lg_match(const float* __restrict__ qg, const float* __restrict__ kg,
                         float* __restrict__ lgout,
                         const float* __restrict__ qd, const float* __restrict__ kd,
                         bf16* __restrict__ mt, float* __restrict__ pos) {
    __shared__ float qs[128];
    __shared__ float buf[128];
    __shared__ int s_idx;
    int t = threadIdx.x;
    if (blockIdx.x < Bn) {
        int row = blockIdx.x;
        qs[t] = qg[(size_t)row * De + t];
        __syncthreads();
        const float* kp = kg + (size_t)t * De;
        float dot = 0.f;
#pragma unroll 8
        for (int c = 0; c < De; c++) dot = fmaf(qs[c], kp[c], dot);
        float logit = dot * INV_TAU;
        buf[t] = __expf(logit); __syncthreads();
        for (int s = 64; s; s >>= 1) { if (t < s) buf[t] += buf[t + s]; __syncthreads(); }
        if (t == row) lgout[row] = logf(buf[0]) - logit;
    } else {
        int row = blockIdx.x - Bn;
        int b = row / HW;
        qs[t] = qd[(size_t)row * De + t];
        __syncthreads();
        if (t < HW) {
            const float* kp = kd + (size_t)(b * HW + t) * De;
            float d = 0.f;
#pragma unroll 8
            for (int c = 0; c < De; c++) d = fmaf(qs[c], kp[c], d);
            buf[t] = d;
        }
        __syncthreads();
        if (t == 0) {
            float bv = buf[0]; int bi = 0;
            for (int j = 1; j < HW; j++)
                if (buf[j] > bv) { bv = buf[j]; bi = j; }
            s_idx = bi; pos[row] = bv;
        }
        __syncthreads();
        mt[(size_t)row * De + t] = __float2bfloat16(kd[(size_t)(b * HW + s_idx) * De + t]);
    }
}

__global__ void lse_finish(const float* __restrict__ Spart, const float* __restrict__ pos,
                           float* __restrict__ out) {
    int row = blockIdx.x * 256 + threadIdx.x;
    if (row >= Nrow) return;
    float s = 0.f;
#pragma unroll
    for (int j = 0; j < NTILE; j++) s += Spart[(size_t)j * Nrow + row];
    out[row] = logf(s) - pos[row] * INV_TAU;
}

__global__ void final_kernel(const float* __restrict__ lg, const float* __restrict__ ld,
                             float* __restrict__ out) {
    int t = threadIdx.x;
    float s1 = 0.f, s2 = 0.f;
    if (t < Bn) s1 = lg[t];
    for (int j = t; j < Nrow; j += 256) s2 += ld[j];
    __shared__ float r1[256], r2[256];
    r1[t] = s1; r2[t] = s2; __syncthreads();
    for (int o = 128; o; o >>= 1) {
        if (t < o) { r1[t] += r1[t + o]; r2[t] += r2[t + o]; }
        __syncthreads();
    }
    if (t == 0) out[0] = 0.5f * (r1[0] / (float)Bn) + 0.5f * (r2[0] / (float)Nrow);
}

// ========================= host orchestration ================================
extern "C" void kernel_launch(void* const* d_in, const int* in_sizes, int n_in,
                              void* d_out, int out_size) {
    const float* feat_q = (const float*)d_in[0];
    const float* feat_k = (const float*)d_in[1];
    const float* Wg1  = (const float*)d_in[2];   const float* bg1 = (const float*)d_in[3];
    const float* Wg2  = (const float*)d_in[4];   const float* bg2 = (const float*)d_in[5];
    const float* Wd1  = (const float*)d_in[6];   const float* bd1 = (const float*)d_in[7];
    const float* Wd2  = (const float*)d_in[8];   const float* bd2 = (const float*)d_in[9];
    const float* mWg1 = (const float*)d_in[10];  const float* mbg1 = (const float*)d_in[11];
    const float* mWg2 = (const float*)d_in[12];  const float* mbg2 = (const float*)d_in[13];
    const float* mWd1 = (const float*)d_in[14];  const float* mbd1 = (const float*)d_in[15];
    const float* mWd2 = (const float*)d_in[16];  const float* mbd2 = (const float*)d_in[17];
    float* out = (float*)d_out;

    cudaFuncSetAttribute(gemm_mma<1>, cudaFuncAttributeMaxDynamicSharedMemorySize, SM_TOTAL);
    cudaFuncSetAttribute(gemm_mma<2>, cudaFuncAttributeMaxDynamicSharedMemorySize, SM_TOTAL);
    cudaFuncSetAttribute(gemm_mma<3>, cudaFuncAttributeMaxDynamicSharedMemorySize, SM_TOTAL);

#define SYM(p, s) cudaGetSymbolAddress((void**)&p, s)
    bf16 *Wd1T, *mWd1T, *Wg1T, *mWg1T, *Wg2T, *Wd2T, *mWg2T, *mWd2T;
    bf16 *Aq, *Ak, *pq, *pk, *gh, *hid, *qdm, *mt;
    float *Spart, *qg, *kg, *qd, *kd, *pos, *lg, *ld;
    SYM(Wd1T, g_Wd1T); SYM(mWd1T, g_mWd1T); SYM(Wg1T, g_Wg1T); SYM(mWg1T, g_mWg1T);
    SYM(Wg2T, g_Wg2T); SYM(Wd2T, g_Wd2T); SYM(mWg2T, g_mWg2T); SYM(mWd2T, g_mWd2T);
    SYM(Aq, g_Aq); SYM(Ak, g_Ak); SYM(pq, g_pq); SYM(pk, g_pk);
    SYM(gh, g_gh); SYM(hid, g_hid); SYM(qdm, g_qdm); SYM(mt, g_mt);
    SYM(Spart, g_Spart);
    SYM(qg, g_qg); SYM(kg, g_kg); SYM(qd, g_qd); SYM(kd, g_kd);
    SYM(pos, g_pos); SYM(lg, g_lg); SYM(ld, g_ld);
#undef SYM

    // ---- 1. all weight transposes ----
    TP tp;
    tp.W[0] = Wd1;  tp.T[0] = Wd1T;
    tp.W[1] = mWd1; tp.T[1] = mWd1T;
    tp.W[2] = Wg1;  tp.T[2] = Wg1T;
    tp.W[3] = mWg1; tp.T[3] = mWg1T;
    tp.W[4] = Wg2;  tp.T[4] = Wg2T;
    tp.W[5] = Wd2;  tp.T[5] = Wd2T;
    tp.W[6] = mWg2; tp.T[6] = mWg2T;
    tp.W[7] = mWd2; tp.T[7] = mWd2T;
    transpose_all<<<8704, dim3(32, 8)>>>(tp);

    // ---- 2. activations (HW-split) ----
    feat_prep<<<dim3(4, Bn, 2), 256>>>(feat_q, feat_k, Aq, Ak, pq, pk);

    // ---- 3. L1 merged: dense (y<49) + global (y==49), full-K, bias+relu bf16 ----
    {
        GOps o;
        o.op[0] = { Aq, Wd1T,  bd1,  nullptr, hid,                   Nrow };
        o.op[1] = { Ak, mWd1T, mbd1, nullptr, hid + (size_t)Nrow*Dh, Nrow };
        o.op[2] = { pq, Wg1T,  bg1,  nullptr, gh,                    Bn };
        o.op[3] = { pk, mWg1T, mbg1, nullptr, gh + (size_t)Bn*Dh,    Bn };
        gemm_mma<1><<<dim3(Dh/128, NTILE + 1, 2), 256, SM_TOTAL>>>(
            o, Dh, Cc, Cc, 32, 0, 1, NTILE);
    }

    // ---- 4. L2 merged: down-proj + global L2, full-K, bias fp32 direct ----
    {
        GOps o;
        o.op[0] = { hid,                   Wd2T,  bd2,  qd, nullptr, Nrow };
        o.op[1] = { hid + (size_t)Nrow*Dh, mWd2T, mbd2, kd, nullptr, Nrow };
        o.op[2] = { gh,                    Wg2T,  bg2,  qg, nullptr, Bn };
        o.op[3] = { gh + (size_t)Bn*Dh,    mWg2T, mbg2, kg, nullptr, Bn };
        gemm_mma<3><<<dim3(1, NTILE + 1, 2), 256, SM_TOTAL>>>(
            o, De, Dh, Dh, 32, 0, 1, NTILE);
    }

    // ---- 5. merged l2norm ----
    l2norm_all<<<(2*Bn + 2*Nrow)/8, dim3(32, 8)>>>(qg, kg, qd, kd, qdm);

    // ---- 6. merged lg + match ----
    lg_match<<<Bn + Nrow, 128>>>(qg, kg, lg, qd, kd, mt, pos);

    // ---- 7. S-GEMM with fused exp epilogue (K=128 -> 2 chunks) ----
    {
        GOps o;
        o.op[0] = { qdm, mt, nullptr, Spart, nullptr, Nrow };
        o.op[1] = o.op[0]; o.op[2] = o.op[0]; o.op[3] = o.op[0];
        gemm_mma<2><<<dim3(NTILE, NTILE, 1), 256, SM_TOTAL>>>(
            o, Nrow, De, De, 2, 0, 1, -1);
    }

    // ---- 8/9. finish ----
    lse_finish<<<(Nrow + 255)/256, 256>>>(Spart, pos, ld);
    final_kernel<<<1, 256>>>(lg, ld, out);
}